// round 7
// baseline (speedup 1.0000x reference)
#include <cuda_runtime.h>
#include <cuda_bf16.h>
#include <cstdint>

#define T_STEPS 1024
#define BATCH   512
#define DIM     128
#define GATES   384

// ---------------- device scratch ----------------
__device__ float g_bc[GATES];
__device__ __nv_bfloat16 g_Bh[3 * 16384];                // Wc hi: [nt][row][k]
__device__ __nv_bfloat16 g_Bl[3 * 16384];                // Wc lo
__device__ float g_GI[(size_t)T_STEPS * BATCH * GATES];  // 805 MB scratch

// ---------------- helpers ----------------
__device__ __forceinline__ float tanhf_fast(float x) {
    float y; asm("tanh.approx.f32 %0, %1;" : "=f"(y) : "f"(x)); return y;
}
__device__ __forceinline__ float sigm_fast(float x) {
    return fmaf(0.5f, tanhf_fast(0.5f * x), 0.5f);
}
__device__ __forceinline__ uint32_t smem_u32(const void* p) {
    uint32_t a;
    asm("{ .reg .u64 t; cvta.to.shared.u64 t, %1; cvt.u32.u64 %0, t; }" : "=r"(a) : "l"(p));
    return a;
}
__device__ __forceinline__ void ldsm4(uint32_t& r0, uint32_t& r1, uint32_t& r2, uint32_t& r3,
                                      uint32_t addr) {
    asm volatile("ldmatrix.sync.aligned.m8n8.x4.shared.b16 {%0,%1,%2,%3}, [%4];"
                 : "=r"(r0), "=r"(r1), "=r"(r2), "=r"(r3) : "r"(addr));
}
__device__ __forceinline__ void ldsm2t(uint32_t& r0, uint32_t& r1, uint32_t addr) {
    asm volatile("ldmatrix.sync.aligned.m8n8.x2.trans.shared.b16 {%0,%1}, [%2];"
                 : "=r"(r0), "=r"(r1) : "r"(addr));
}
__device__ __forceinline__ void mma16816(float* c, const uint32_t* a, uint32_t b0, uint32_t b1) {
    asm volatile(
        "mma.sync.aligned.m16n8k16.row.col.f32.bf16.bf16.f32 "
        "{%0,%1,%2,%3}, {%4,%5,%6,%7}, {%8,%9}, {%0,%1,%2,%3};"
        : "+f"(c[0]), "+f"(c[1]), "+f"(c[2]), "+f"(c[3])
        : "r"(a[0]), "r"(a[1]), "r"(a[2]), "r"(a[3]), "r"(b0), "r"(b1));
}
__device__ __forceinline__ void split_bf16(float v, __nv_bfloat16& h, __nv_bfloat16& l) {
    h = __float2bfloat16(v);
    l = __float2bfloat16(v - __bfloat162float(h));
}
__device__ __forceinline__ uint32_t cluster_rank() {
    uint32_t r; asm("mov.u32 %0, %%cluster_ctarank;" : "=r"(r)); return r;
}
__device__ __forceinline__ uint32_t mapa_u32(uint32_t addr, uint32_t rank) {
    uint32_t r;
    asm("mapa.shared::cluster.u32 %0, %1, %2;" : "=r"(r) : "r"(addr), "r"(rank));
    return r;
}
__device__ __forceinline__ void st_cluster_u16(uint32_t addr, unsigned short v) {
    asm volatile("st.shared::cluster.u16 [%0], %1;" :: "r"(addr), "h"(v) : "memory");
}
#define CLUSTER_ARRIVE() asm volatile("barrier.cluster.arrive.aligned;" ::: "memory")
#define CLUSTER_WAIT()   asm volatile("barrier.cluster.wait.aligned;" ::: "memory")

// ---------------- prep: fold fc1 into Wc (bf16 hi/lo) + bc ----------------
__global__ void prep_kernel(const float* __restrict__ W1, const float* __restrict__ b1,
                            const float* __restrict__ W_ih, const float* __restrict__ b_ih) {
    int bid = blockIdx.x, tid = threadIdx.x;
    __shared__ float wih[DIM];
    __shared__ float red[DIM];
    wih[tid] = W_ih[bid * DIM + tid];
    __syncthreads();
    float acc = 0.f;
    #pragma unroll 8
    for (int k = 0; k < DIM; k++)
        acc = fmaf(wih[k], W1[k * DIM + tid], acc);
    __nv_bfloat16 h, l;
    split_bf16(acc, h, l);
    g_Bh[bid * DIM + tid] = h;
    g_Bl[bid * DIM + tid] = l;
    red[tid] = wih[tid] * b1[tid];
    __syncthreads();
    if (tid == 0) {
        float s = 0.f;
        for (int k = 0; k < DIM; k++) s += red[k];
        g_bc[bid] = s + b_ih[bid];
    }
}

// ---------------- HMMA GI GEMM (unchanged from R5) ----------------
#define GSM_BC  0
#define GSM_AH  1024
#define GSM_AL  (GSM_AH + 64 * 272)
#define GSM_BH  (GSM_AL + 64 * 272)
#define GSM_BL  (GSM_BH + 128 * 272)
#define GSMEM   (GSM_BL + 128 * 272)

__global__ __launch_bounds__(256, 2)
void gi_gemm_hmma(const float* __restrict__ X) {
    extern __shared__ char smem[];
    const uint32_t sbase = smem_u32(smem);
    const int tid = threadIdx.x;
    const int wid = tid >> 5, lane = tid & 31;
    const int nt = blockIdx.x;
    const int n0 = nt * 128;
    const int m0 = blockIdx.y * 64;

    const float4* Xf4 = (const float4*)X;
    #pragma unroll 4
    for (int s = tid; s < 2048; s += 256) {
        int row = s >> 5, q = s & 31;
        float4 v = Xf4[(size_t)(m0 + row) * 32 + q];
        __nv_bfloat16 h0, h1, h2, h3, l0, l1, l2, l3;
        split_bf16(v.x, h0, l0); split_bf16(v.y, h1, l1);
        split_bf16(v.z, h2, l2); split_bf16(v.w, h3, l3);
        __nv_bfloat162 hA(h0, h1), hB(h2, h3), lA(l0, l1), lB(l2, l3);
        int off = row * 272 + q * 8;
        *(uint2*)(smem + GSM_AH + off) = make_uint2(*(uint32_t*)&hA, *(uint32_t*)&hB);
        *(uint2*)(smem + GSM_AL + off) = make_uint2(*(uint32_t*)&lA, *(uint32_t*)&lB);
    }
    const uint4* Bh4 = (const uint4*)(g_Bh + nt * 16384);
    const uint4* Bl4 = (const uint4*)(g_Bl + nt * 16384);
    #pragma unroll 4
    for (int s = tid; s < 2048; s += 256) {
        int row = s >> 4, u = s & 15;
        int off = row * 272 + u * 16;
        *(uint4*)(smem + GSM_BH + off) = Bh4[s];
        *(uint4*)(smem + GSM_BL + off) = Bl4[s];
    }
    if (tid < 128) *(float*)(smem + GSM_BC + tid * 4) = g_bc[n0 + tid];
    __syncthreads();

    const int wm = wid & 1;
    const int wn = wid >> 1;
    const uint32_t aoff = (uint32_t)(wm * 32 + (lane & 15)) * 272 + ((lane >> 4) << 4);
    const uint32_t boff = (uint32_t)(wn * 32 + (lane & 7) + ((lane >> 4) << 3)) * 272
                        + (((lane >> 3) & 1) << 4);

    float C[2][4][4];
    #pragma unroll
    for (int mf = 0; mf < 2; mf++)
        #pragma unroll
        for (int nf = 0; nf < 4; nf++)
            #pragma unroll
            for (int q = 0; q < 4; q++) C[mf][nf][q] = 0.f;

    const uint32_t abase[3] = { sbase + GSM_AH, sbase + GSM_AH, sbase + GSM_AL };
    const uint32_t bbase[3] = { sbase + GSM_BH, sbase + GSM_BL, sbase + GSM_BH };

    #pragma unroll
    for (int p = 0; p < 3; p++) {
        const uint32_t ab = abase[p] + aoff;
        const uint32_t bb = bbase[p] + boff;
        #pragma unroll
        for (int ks = 0; ks < 8; ks++) {
            uint32_t a[2][4], b[2][4];
            ldsm4(a[0][0], a[0][1], a[0][2], a[0][3], ab + ks * 32);
            ldsm4(a[1][0], a[1][1], a[1][2], a[1][3], ab + 16 * 272 + ks * 32);
            ldsm4(b[0][0], b[0][1], b[0][2], b[0][3], bb + ks * 32);
            ldsm4(b[1][0], b[1][1], b[1][2], b[1][3], bb + 16 * 272 + ks * 32);
            #pragma unroll
            for (int mf = 0; mf < 2; mf++) {
                mma16816(C[mf][0], a[mf], b[0][0], b[0][1]);
                mma16816(C[mf][1], a[mf], b[0][2], b[0][3]);
                mma16816(C[mf][2], a[mf], b[1][0], b[1][1]);
                mma16816(C[mf][3], a[mf], b[1][2], b[1][3]);
            }
        }
    }

    const float* bcs = (const float*)(smem + GSM_BC);
    const int qrow = lane >> 2, qcol = (lane & 3) * 2;
    #pragma unroll
    for (int mf = 0; mf < 2; mf++) {
        int row = m0 + wm * 32 + mf * 16 + qrow;
        #pragma unroll
        for (int nf = 0; nf < 4; nf++) {
            int colL = wn * 32 + nf * 8 + qcol;
            float b0 = bcs[colL], b1 = bcs[colL + 1];
            float* d0 = g_GI + (size_t)row * GATES + n0 + colL;
            *(float2*)d0 = make_float2(C[mf][nf][0] + b0, C[mf][nf][1] + b1);
            float* d1 = g_GI + (size_t)(row + 8) * GATES + n0 + colL;
            *(float2*)d1 = make_float2(C[mf][nf][2] + b0, C[mf][nf][3] + b1);
        }
    }
}

// ---------------- cluster GRU scan: 64 clusters x 2 CTAs, 8 batch rows/cluster ----
// CTA rank owns j in [rank*64, rank*64+64): 12 m16-tiles (3 gates x 4), 12 warps.
// W (bf16 hi/lo) rows padded 272B; h ping-pong [cur][hi/lo][128 j][8 b] bf16.
#define CW_HI  0
#define CW_LO  52224
#define CH     104448               // 2 x (2KB hi + 2KB lo) = 8192
#define CSC    (CH + 8192)          // scratch 192 rows x 9 floats = 6912
#define CSMEM  (CSC + 6912)

__global__ __launch_bounds__(384, 1) __cluster_dims__(2, 1, 1)
void gru_scan_cluster(const float* __restrict__ W_hh, const float* __restrict__ b_hh,
                      float* __restrict__ out) {
    extern __shared__ char smem[];
    const uint32_t sbase = smem_u32(smem);
    const int tid = threadIdx.x, wt = tid >> 5, lane = tid & 31;
    const uint32_t rank = cluster_rank();
    const int r0 = (blockIdx.x >> 1) * 8;           // 8 batch rows per cluster

    // ---- stage W_hh (this CTA's 192 rows) as bf16 hi/lo ----
    for (int s = tid; s < 6144; s += 384) {
        int row_local = s >> 5, q = s & 31;
        int g = row_local >> 6, jloc = row_local & 63;
        int grow = g * 128 + (int)rank * 64 + jloc;
        float4 v = ((const float4*)W_hh)[grow * 32 + q];
        __nv_bfloat16 h0, h1, h2, h3, l0, l1, l2, l3;
        split_bf16(v.x, h0, l0); split_bf16(v.y, h1, l1);
        split_bf16(v.z, h2, l2); split_bf16(v.w, h3, l3);
        __nv_bfloat162 hA(h0, h1), hB(h2, h3), lA(l0, l1), lB(l2, l3);
        int off = row_local * 272 + q * 8;
        *(uint2*)(smem + CW_HI + off) = make_uint2(*(uint32_t*)&hA, *(uint32_t*)&hB);
        *(uint2*)(smem + CW_LO + off) = make_uint2(*(uint32_t*)&lA, *(uint32_t*)&lB);
    }
    // zero h buffers (both phases, hi+lo)
    for (int s = tid; s < 2048; s += 384)
        ((uint32_t*)(smem + CH))[s] = 0;
    __syncthreads();
    CLUSTER_ARRIVE(); CLUSTER_WAIT();   // peer staging done before any remote h writes

    // ---- per-warp tile: g = wt/4, jt = (wt%4)*16 ----
    const int g = wt >> 2, jt = (wt & 3) << 4;
    // preload W fragments (loop-invariant)
    uint32_t wh[8][4], wl[8][4];
    {
        uint32_t ab = sbase + CW_HI + (uint32_t)(g * 64 + jt + (lane & 15)) * 272
                    + ((lane >> 4) << 4);
        #pragma unroll
        for (int ks = 0; ks < 8; ks++)
            ldsm4(wh[ks][0], wh[ks][1], wh[ks][2], wh[ks][3], ab + ks * 32);
        ab += CW_LO - CW_HI;
        #pragma unroll
        for (int ks = 0; ks < 8; ks++)
            ldsm4(wl[ks][0], wl[ks][1], wl[ks][2], wl[ks][3], ab + ks * 32);
    }

    // combine-thread state (tid < 128): jloc = tid&63, 4 batch cols
    const int jloc_c = tid & 63;
    const int jglob = (int)rank * 64 + jloc_c;
    const int bq = (tid >> 6) << 2;                 // 0 or 4
    float br = 0.f, bz = 0.f, bn = 0.f;
    if (tid < 128) {
        br = b_hh[jglob];
        bz = b_hh[DIM + jglob];
        bn = b_hh[2 * DIM + jglob];
    }
    float hprev[4] = {0.f, 0.f, 0.f, 0.f};

    const uint32_t peer_base = mapa_u32(sbase, rank ^ 1);
    float* scp = (float*)(smem + CSC);
    const int jq = lane >> 2, c0 = 2 * (lane & 3);
    const int scrow = g * 64 + jt + jq;

    for (int t = 0; t < T_STEPS; t++) {
        const int cur = t & 1;

        // prefetch input gates (combine threads)
        float giv[3][4];
        if (tid < 128) {
            #pragma unroll
            for (int i = 0; i < 4; i++) {
                size_t base = ((size_t)t * BATCH + r0 + bq + i) * GATES + jglob;
                giv[0][i] = g_GI[base];
                giv[1][i] = g_GI[base + DIM];
                giv[2][i] = g_GI[base + 2 * DIM];
            }
        }

        // B fragments (h hi/lo)
        uint32_t bhf[8][2], blf[8][2];
        {
            uint32_t hb = sbase + CH + (uint32_t)cur * 4096 + (lane & 15) * 16;
            #pragma unroll
            for (int ks = 0; ks < 8; ks++) {
                ldsm2t(bhf[ks][0], bhf[ks][1], hb + ks * 256);
                ldsm2t(blf[ks][0], blf[ks][1], hb + 2048 + ks * 256);
            }
        }

        float C[4] = {0.f, 0.f, 0.f, 0.f};
        #pragma unroll
        for (int ks = 0; ks < 8; ks++) {
            mma16816(C, wh[ks], bhf[ks][0], bhf[ks][1]);
            mma16816(C, wh[ks], blf[ks][0], blf[ks][1]);
            mma16816(C, wl[ks], bhf[ks][0], bhf[ks][1]);
        }

        // publish gate values to scratch (rows stride 9 floats: conflict-free reads)
        scp[scrow * 9 + c0]           = C[0];
        scp[scrow * 9 + c0 + 1]       = C[1];
        scp[(scrow + 8) * 9 + c0]     = C[2];
        scp[(scrow + 8) * 9 + c0 + 1] = C[3];
        __syncthreads();

        if (tid < 128) {
            const int nxt = cur ^ 1;
            #pragma unroll
            for (int i = 0; i < 4; i++) {
                int b = bq + i;
                float gr = scp[(jloc_c) * 9 + b];
                float gz = scp[(64 + jloc_c) * 9 + b];
                float gn = scp[(128 + jloc_c) * 9 + b];
                float r = sigm_fast(gr + br + giv[0][i]);
                float z = sigm_fast(gz + bz + giv[1][i]);
                float n = tanhf_fast(giv[2][i] + r * (gn + bn));
                float h = n + z * (hprev[i] - n);
                hprev[i] = h;
                __nv_bfloat16 hh, hl;
                split_bf16(h, hh, hl);
                uint32_t off = CH + (uint32_t)nxt * 4096 + (uint32_t)jglob * 16 + b * 2;
                *(__nv_bfloat16*)(smem + off) = hh;
                *(__nv_bfloat16*)(smem + off + 2048) = hl;
                st_cluster_u16(peer_base + off, *(unsigned short*)&hh);
                st_cluster_u16(peer_base + off + 2048, *(unsigned short*)&hl);
            }
        }
        CLUSTER_ARRIVE();
        CLUSTER_WAIT();
    }

    if (tid < 128) {
        #pragma unroll
        for (int i = 0; i < 4; i++)
            out[(r0 + bq + i) * DIM + jglob] = hprev[i];
    }
}

// ---------------- launch ----------------
extern "C" void kernel_launch(void* const* d_in, const int* in_sizes, int n_in,
                              void* d_out, int out_size) {
    const float* x    = (const float*)d_in[0];
    const float* W1   = (const float*)d_in[1];
    const float* b1   = (const float*)d_in[2];
    const float* W_ih = (const float*)d_in[3];
    const float* W_hh = (const float*)d_in[4];
    const float* b_ih = (const float*)d_in[5];
    const float* b_hh = (const float*)d_in[6];
    float* out = (float*)d_out;

    static bool attr_done = false;
    if (!attr_done) {
        cudaFuncSetAttribute(gi_gemm_hmma,
                             cudaFuncAttributeMaxDynamicSharedMemorySize, GSMEM);
        cudaFuncSetAttribute(gru_scan_cluster,
                             cudaFuncAttributeMaxDynamicSharedMemorySize, CSMEM);
        attr_done = true;
    }

    prep_kernel<<<GATES, DIM>>>(W1, b1, W_ih, b_ih);
    gi_gemm_hmma<<<dim3(3, 8192), 256, GSMEM>>>(x);
    gru_scan_cluster<<<128, 384, CSMEM>>>(W_hh, b_hh, out);
}

// round 8
// speedup vs baseline: 1.3944x; 1.3944x over previous
#include <cuda_runtime.h>
#include <cuda_bf16.h>
#include <cstdint>

#define T_STEPS 1024
#define BATCH   512
#define DIM     128
#define GATES   384

// ---------------- device scratch ----------------
__device__ float g_bc[GATES];
__device__ __nv_bfloat16 g_Bh[3 * 16384];                // Wc hi: [nt][row][k]
__device__ __nv_bfloat16 g_Bl[3 * 16384];                // Wc lo
__device__ float g_GI[(size_t)T_STEPS * BATCH * GATES];  // 805 MB scratch

// ---------------- helpers ----------------
__device__ __forceinline__ float tanhf_fast(float x) {
    float y; asm("tanh.approx.f32 %0, %1;" : "=f"(y) : "f"(x)); return y;
}
__device__ __forceinline__ float sigm_fast(float x) {
    return fmaf(0.5f, tanhf_fast(0.5f * x), 0.5f);
}
__device__ __forceinline__ uint32_t smem_u32(const void* p) {
    uint32_t a;
    asm("{ .reg .u64 t; cvta.to.shared.u64 t, %1; cvt.u32.u64 %0, t; }" : "=r"(a) : "l"(p));
    return a;
}
__device__ __forceinline__ void ldsm4(uint32_t& r0, uint32_t& r1, uint32_t& r2, uint32_t& r3,
                                      uint32_t addr) {
    asm volatile("ldmatrix.sync.aligned.m8n8.x4.shared.b16 {%0,%1,%2,%3}, [%4];"
                 : "=r"(r0), "=r"(r1), "=r"(r2), "=r"(r3) : "r"(addr));
}
__device__ __forceinline__ void ldsm2t(uint32_t& r0, uint32_t& r1, uint32_t addr) {
    asm volatile("ldmatrix.sync.aligned.m8n8.x2.trans.shared.b16 {%0,%1}, [%2];"
                 : "=r"(r0), "=r"(r1) : "r"(addr));
}
__device__ __forceinline__ void mma16816(float* c, const uint32_t* a, uint32_t b0, uint32_t b1) {
    asm volatile(
        "mma.sync.aligned.m16n8k16.row.col.f32.bf16.bf16.f32 "
        "{%0,%1,%2,%3}, {%4,%5,%6,%7}, {%8,%9}, {%0,%1,%2,%3};"
        : "+f"(c[0]), "+f"(c[1]), "+f"(c[2]), "+f"(c[3])
        : "r"(a[0]), "r"(a[1]), "r"(a[2]), "r"(a[3]), "r"(b0), "r"(b1));
}
__device__ __forceinline__ void split_bf16(float v, __nv_bfloat16& h, __nv_bfloat16& l) {
    h = __float2bfloat16(v);
    l = __float2bfloat16(v - __bfloat162float(h));
}

// ---------------- prep: fold fc1 into Wc (bf16 hi/lo) + bc ----------------
__global__ void prep_kernel(const float* __restrict__ W1, const float* __restrict__ b1,
                            const float* __restrict__ W_ih, const float* __restrict__ b_ih) {
    int bid = blockIdx.x, tid = threadIdx.x;
    __shared__ float wih[DIM];
    __shared__ float red[DIM];
    wih[tid] = W_ih[bid * DIM + tid];
    __syncthreads();
    float acc = 0.f;
    #pragma unroll 8
    for (int k = 0; k < DIM; k++)
        acc = fmaf(wih[k], W1[k * DIM + tid], acc);
    __nv_bfloat16 h, l;
    split_bf16(acc, h, l);
    g_Bh[bid * DIM + tid] = h;
    g_Bl[bid * DIM + tid] = l;
    red[tid] = wih[tid] * b1[tid];
    __syncthreads();
    if (tid == 0) {
        float s = 0.f;
        for (int k = 0; k < DIM; k++) s += red[k];
        g_bc[bid] = s + b_ih[bid];
    }
}

// ---------------- HMMA GI GEMM (unchanged, occ 2) ----------------
#define GSM_BC  0
#define GSM_AH  1024
#define GSM_AL  (GSM_AH + 64 * 272)
#define GSM_BH  (GSM_AL + 64 * 272)
#define GSM_BL  (GSM_BH + 128 * 272)
#define GSMEM   (GSM_BL + 128 * 272)

__global__ __launch_bounds__(256, 2)
void gi_gemm_hmma(const float* __restrict__ X) {
    extern __shared__ char smem[];
    const uint32_t sbase = smem_u32(smem);
    const int tid = threadIdx.x;
    const int wid = tid >> 5, lane = tid & 31;
    const int nt = blockIdx.x;
    const int n0 = nt * 128;
    const int m0 = blockIdx.y * 64;

    const float4* Xf4 = (const float4*)X;
    #pragma unroll 4
    for (int s = tid; s < 2048; s += 256) {
        int row = s >> 5, q = s & 31;
        float4 v = Xf4[(size_t)(m0 + row) * 32 + q];
        __nv_bfloat16 h0, h1, h2, h3, l0, l1, l2, l3;
        split_bf16(v.x, h0, l0); split_bf16(v.y, h1, l1);
        split_bf16(v.z, h2, l2); split_bf16(v.w, h3, l3);
        __nv_bfloat162 hA(h0, h1), hB(h2, h3), lA(l0, l1), lB(l2, l3);
        int off = row * 272 + q * 8;
        *(uint2*)(smem + GSM_AH + off) = make_uint2(*(uint32_t*)&hA, *(uint32_t*)&hB);
        *(uint2*)(smem + GSM_AL + off) = make_uint2(*(uint32_t*)&lA, *(uint32_t*)&lB);
    }
    const uint4* Bh4 = (const uint4*)(g_Bh + nt * 16384);
    const uint4* Bl4 = (const uint4*)(g_Bl + nt * 16384);
    #pragma unroll 4
    for (int s = tid; s < 2048; s += 256) {
        int row = s >> 4, u = s & 15;
        int off = row * 272 + u * 16;
        *(uint4*)(smem + GSM_BH + off) = Bh4[s];
        *(uint4*)(smem + GSM_BL + off) = Bl4[s];
    }
    if (tid < 128) *(float*)(smem + GSM_BC + tid * 4) = g_bc[n0 + tid];
    __syncthreads();

    const int wm = wid & 1;
    const int wn = wid >> 1;
    const uint32_t aoff = (uint32_t)(wm * 32 + (lane & 15)) * 272 + ((lane >> 4) << 4);
    const uint32_t boff = (uint32_t)(wn * 32 + (lane & 7) + ((lane >> 4) << 3)) * 272
                        + (((lane >> 3) & 1) << 4);

    float C[2][4][4];
    #pragma unroll
    for (int mf = 0; mf < 2; mf++)
        #pragma unroll
        for (int nf = 0; nf < 4; nf++)
            #pragma unroll
            for (int q = 0; q < 4; q++) C[mf][nf][q] = 0.f;

    const uint32_t abase[3] = { sbase + GSM_AH, sbase + GSM_AH, sbase + GSM_AL };
    const uint32_t bbase[3] = { sbase + GSM_BH, sbase + GSM_BL, sbase + GSM_BH };

    #pragma unroll
    for (int p = 0; p < 3; p++) {
        const uint32_t ab = abase[p] + aoff;
        const uint32_t bb = bbase[p] + boff;
        #pragma unroll
        for (int ks = 0; ks < 8; ks++) {
            uint32_t a[2][4], b[2][4];
            ldsm4(a[0][0], a[0][1], a[0][2], a[0][3], ab + ks * 32);
            ldsm4(a[1][0], a[1][1], a[1][2], a[1][3], ab + 16 * 272 + ks * 32);
            ldsm4(b[0][0], b[0][1], b[0][2], b[0][3], bb + ks * 32);
            ldsm4(b[1][0], b[1][1], b[1][2], b[1][3], bb + 16 * 272 + ks * 32);
            #pragma unroll
            for (int mf = 0; mf < 2; mf++) {
                mma16816(C[mf][0], a[mf], b[0][0], b[0][1]);
                mma16816(C[mf][1], a[mf], b[0][2], b[0][3]);
                mma16816(C[mf][2], a[mf], b[1][0], b[1][1]);
                mma16816(C[mf][3], a[mf], b[1][2], b[1][3]);
            }
        }
    }

    const float* bcs = (const float*)(smem + GSM_BC);
    const int qrow = lane >> 2, qcol = (lane & 3) * 2;
    #pragma unroll
    for (int mf = 0; mf < 2; mf++) {
        int row = m0 + wm * 32 + mf * 16 + qrow;
        #pragma unroll
        for (int nf = 0; nf < 4; nf++) {
            int colL = wn * 32 + nf * 8 + qcol;
            float b0 = bcs[colL], b1 = bcs[colL + 1];
            float* d0 = g_GI + (size_t)row * GATES + n0 + colL;
            *(float2*)d0 = make_float2(C[mf][nf][0] + b0, C[mf][nf][1] + b1);
            float* d1 = g_GI + (size_t)(row + 8) * GATES + n0 + colL;
            *(float2*)d1 = make_float2(C[mf][nf][2] + b0, C[mf][nf][3] + b1);
        }
    }
}

// ---------------- HMMA GRU scan v3: h_lo packed into n-cols 4-7 ----------------
// 128 blocks x 4 batch rows, 256 threads. Warp w owns j in [16w,16w+16) for all
// 3 gates. B frag = [k rows][cols 0-3 h_hi(b), cols 4-7 h_lo(b)] 16B rows,
// ping-pong 2 phases. 2 mma passes (A = W_hi, W_lo); epilogue: add passes +
// shfl.xor(2) fold -> full W*h. 384 mma/step.
#define SW_HI  0
#define SW_LO  104448               // 384 rows * 272 B
#define SH     208896               // 2 phases x 2048 B
#define SSMEM  (SH + 4096)

__global__ __launch_bounds__(256, 1)
void gru_scan_hmma(const float* __restrict__ W_hh, const float* __restrict__ b_hh,
                   float* __restrict__ out) {
    extern __shared__ char smem[];
    const uint32_t sbase = smem_u32(smem);
    const int tid = threadIdx.x, w = tid >> 5, lane = tid & 31;
    const int r0 = blockIdx.x * 4;

    // stage W_hh -> bf16 hi/lo, 272B-padded rows (384 x 128)
    #pragma unroll 4
    for (int s = tid; s < 12288; s += 256) {
        int row = s >> 5, q = s & 31;
        float4 v = ((const float4*)W_hh)[s];
        __nv_bfloat16 h0, h1, h2, h3, l0, l1, l2, l3;
        split_bf16(v.x, h0, l0); split_bf16(v.y, h1, l1);
        split_bf16(v.z, h2, l2); split_bf16(v.w, h3, l3);
        __nv_bfloat162 hA(h0, h1), hB(h2, h3), lA(l0, l1), lB(l2, l3);
        int off = row * 272 + q * 8;
        *(uint2*)(smem + SW_HI + off) = make_uint2(*(uint32_t*)&hA, *(uint32_t*)&hB);
        *(uint2*)(smem + SW_LO + off) = make_uint2(*(uint32_t*)&lA, *(uint32_t*)&lB);
    }
    // zero phase 0 of h buffer
    for (int s = tid; s < 512; s += 256)
        ((uint32_t*)(smem + SH))[s] = 0;
    __syncthreads();

    // lane -> (j, b) mapping for folded D frags
    const int jq = lane >> 2;
    const int j0 = 16 * w + jq, j1 = j0 + 8;
    const int bsel = lane & 3;
    const bool valid = (bsel < 2);
    const int b0 = 2 * bsel, b1 = b0 + 1;         // valid lanes: b pairs {0,1},{2,3}

    const float br0 = b_hh[j0],           br1 = b_hh[j1];
    const float bz0 = b_hh[DIM + j0],     bz1 = b_hh[DIM + j1];
    const float bn0 = b_hh[2 * DIM + j0], bn1 = b_hh[2 * DIM + j1];

    // A ldmatrix base: rows 16w + (lane&15) within gate block g (+g*128 rows)
    const uint32_t a_base = sbase + SW_HI
        + (uint32_t)(16 * w + (lane & 15)) * 272 + ((lane >> 4) << 4);
    const uint32_t bf_base = sbase + SH + (uint32_t)(lane & 15) * 16;

    float hprev[4] = {0.f, 0.f, 0.f, 0.f};

    for (int t = 0; t < T_STEPS; t++) {
        const int cur = t & 1;

        // prefetch input gates (valid lanes): 12 LDG, latency hidden under mma
        float giv[3][4];
        #pragma unroll
        for (int q = 0; q < 4; q++) {
            if (valid) {
                int j = (q & 2) ? j1 : j0;
                int b = b0 + (q & 1);
                size_t base = ((size_t)t * BATCH + r0 + b) * GATES + j;
                giv[0][q] = g_GI[base];
                giv[1][q] = g_GI[base + DIM];
                giv[2][q] = g_GI[base + 2 * DIM];
            } else {
                giv[0][q] = giv[1][q] = giv[2][q] = 0.f;
            }
        }

        // B frags: one buffer, cols 0-3 = h_hi, 4-7 = h_lo
        uint32_t bf[8][2];
        {
            const uint32_t hb = bf_base + (uint32_t)cur * 2048;
            #pragma unroll
            for (int ks = 0; ks < 8; ks++)
                ldsm2t(bf[ks][0], bf[ks][1], hb + ks * 256);
        }

        float C[3][2][4];
        #pragma unroll
        for (int g = 0; g < 3; g++)
            #pragma unroll
            for (int p = 0; p < 2; p++)
                #pragma unroll
                for (int q = 0; q < 4; q++) C[g][p][q] = 0.f;

        #pragma unroll
        for (int g = 0; g < 3; g++) {
            #pragma unroll
            for (int p = 0; p < 2; p++) {
                const uint32_t ag = a_base + (uint32_t)g * (128 * 272)
                                  + (uint32_t)p * SW_LO;
                #pragma unroll
                for (int ks = 0; ks < 8; ks++) {
                    uint32_t a[4];
                    ldsm4(a[0], a[1], a[2], a[3], ag + ks * 32);
                    mma16816(C[g][p], a, bf[ks][0], bf[ks][1]);
                }
            }
        }

        // fold: add W_hi/W_lo passes (same col), then xor-2 shuffle folds h_lo cols
        float G[3][4];
        #pragma unroll
        for (int g = 0; g < 3; g++)
            #pragma unroll
            for (int q = 0; q < 4; q++) {
                float s = C[g][0][q] + C[g][1][q];
                s += __shfl_xor_sync(0xffffffffu, s, 2);
                G[g][q] = s;
            }

        // gates (all lanes compute; only valid lanes' results used)
        float hnew[4];
        #pragma unroll
        for (int q = 0; q < 4; q++) {
            float br = (q & 2) ? br1 : br0;
            float bz = (q & 2) ? bz1 : bz0;
            float bn = (q & 2) ? bn1 : bn0;
            float r = sigm_fast(G[0][q] + br + giv[0][q]);
            float z = sigm_fast(G[1][q] + bz + giv[1][q]);
            float n = tanhf_fast(giv[2][q] + r * (G[2][q] + bn));
            hnew[q] = n + z * (hprev[q] - n);
            hprev[q] = hnew[q];
        }

        // publish new h (valid lanes) into next phase: hi bytes 0-7, lo bytes 8-15
        if (valid) {
            const uint32_t nb = SH + (uint32_t)(cur ^ 1) * 2048;
            #pragma unroll
            for (int q = 0; q < 4; q++) {
                int j = (q & 2) ? j1 : j0;
                int b = b0 + (q & 1);
                __nv_bfloat16 hh, hl;
                split_bf16(hnew[q], hh, hl);
                *(__nv_bfloat16*)(smem + nb + j * 16 + b * 2) = hh;
                *(__nv_bfloat16*)(smem + nb + j * 16 + 8 + b * 2) = hl;
            }
        }
        __syncthreads();
    }

    if (valid) {
        #pragma unroll
        for (int q = 0; q < 4; q++) {
            int j = (q & 2) ? j1 : j0;
            int b = b0 + (q & 1);
            out[(r0 + b) * DIM + j] = hprev[q];
        }
    }
}

// ---------------- launch ----------------
extern "C" void kernel_launch(void* const* d_in, const int* in_sizes, int n_in,
                              void* d_out, int out_size) {
    const float* x    = (const float*)d_in[0];
    const float* W1   = (const float*)d_in[1];
    const float* b1   = (const float*)d_in[2];
    const float* W_ih = (const float*)d_in[3];
    const float* W_hh = (const float*)d_in[4];
    const float* b_ih = (const float*)d_in[5];
    const float* b_hh = (const float*)d_in[6];
    float* out = (float*)d_out;

    static bool attr_done = false;
    if (!attr_done) {
        cudaFuncSetAttribute(gi_gemm_hmma,
                             cudaFuncAttributeMaxDynamicSharedMemorySize, GSMEM);
        cudaFuncSetAttribute(gru_scan_hmma,
                             cudaFuncAttributeMaxDynamicSharedMemorySize, SSMEM);
        attr_done = true;
    }

    prep_kernel<<<GATES, DIM>>>(W1, b1, W_ih, b_ih);
    gi_gemm_hmma<<<dim3(3, 8192), 256, GSMEM>>>(x);
    gru_scan_hmma<<<128, 256, SSMEM>>>(W_hh, b_hh, out);
}

// round 9
// speedup vs baseline: 1.5754x; 1.1298x over previous
#include <cuda_runtime.h>
#include <cuda_bf16.h>
#include <cstdint>

#define T_STEPS 1024
#define BATCH   512
#define DIM     128
#define GATES   384

// ---------------- device scratch ----------------
__device__ float g_bc[GATES];
__device__ __nv_bfloat16 g_Bh[3 * 16384];                // Wc hi: [nt][row][k]
__device__ __nv_bfloat16 g_Bl[3 * 16384];                // Wc lo
__device__ float g_GI[(size_t)T_STEPS * BATCH * GATES];  // 805 MB scratch

// ---------------- helpers ----------------
__device__ __forceinline__ float tanhf_fast(float x) {
    float y; asm("tanh.approx.f32 %0, %1;" : "=f"(y) : "f"(x)); return y;
}
__device__ __forceinline__ float sigm_fast(float x) {
    return fmaf(0.5f, tanhf_fast(0.5f * x), 0.5f);
}
__device__ __forceinline__ uint32_t smem_u32(const void* p) {
    uint32_t a;
    asm("{ .reg .u64 t; cvta.to.shared.u64 t, %1; cvt.u32.u64 %0, t; }" : "=r"(a) : "l"(p));
    return a;
}
__device__ __forceinline__ void ldsm4(uint32_t& r0, uint32_t& r1, uint32_t& r2, uint32_t& r3,
                                      uint32_t addr) {
    asm volatile("ldmatrix.sync.aligned.m8n8.x4.shared.b16 {%0,%1,%2,%3}, [%4];"
                 : "=r"(r0), "=r"(r1), "=r"(r2), "=r"(r3) : "r"(addr));
}
__device__ __forceinline__ void ldsm2t(uint32_t& r0, uint32_t& r1, uint32_t addr) {
    asm volatile("ldmatrix.sync.aligned.m8n8.x2.trans.shared.b16 {%0,%1}, [%2];"
                 : "=r"(r0), "=r"(r1) : "r"(addr));
}
__device__ __forceinline__ void mma16816(float* c, const uint32_t* a, uint32_t b0, uint32_t b1) {
    asm volatile(
        "mma.sync.aligned.m16n8k16.row.col.f32.bf16.bf16.f32 "
        "{%0,%1,%2,%3}, {%4,%5,%6,%7}, {%8,%9}, {%0,%1,%2,%3};"
        : "+f"(c[0]), "+f"(c[1]), "+f"(c[2]), "+f"(c[3])
        : "r"(a[0]), "r"(a[1]), "r"(a[2]), "r"(a[3]), "r"(b0), "r"(b1));
}
__device__ __forceinline__ void split_bf16(float v, __nv_bfloat16& h, __nv_bfloat16& l) {
    h = __float2bfloat16(v);
    l = __float2bfloat16(v - __bfloat162float(h));
}

// ---------------- prep ----------------
__global__ void prep_kernel(const float* __restrict__ W1, const float* __restrict__ b1,
                            const float* __restrict__ W_ih, const float* __restrict__ b_ih) {
    int bid = blockIdx.x, tid = threadIdx.x;
    __shared__ float wih[DIM];
    __shared__ float red[DIM];
    wih[tid] = W_ih[bid * DIM + tid];
    __syncthreads();
    float acc = 0.f;
    #pragma unroll 8
    for (int k = 0; k < DIM; k++)
        acc = fmaf(wih[k], W1[k * DIM + tid], acc);
    __nv_bfloat16 h, l;
    split_bf16(acc, h, l);
    g_Bh[bid * DIM + tid] = h;
    g_Bl[bid * DIM + tid] = l;
    red[tid] = wih[tid] * b1[tid];
    __syncthreads();
    if (tid == 0) {
        float s = 0.f;
        for (int k = 0; k < DIM; k++) s += red[k];
        g_bc[bid] = s + b_ih[bid];
    }
}

// ---------------- HMMA GI GEMM (unchanged, occ 2) ----------------
#define GSM_BC  0
#define GSM_AH  1024
#define GSM_AL  (GSM_AH + 64 * 272)
#define GSM_BH  (GSM_AL + 64 * 272)
#define GSM_BL  (GSM_BH + 128 * 272)
#define GSMEM   (GSM_BL + 128 * 272)

__global__ __launch_bounds__(256, 2)
void gi_gemm_hmma(const float* __restrict__ X) {
    extern __shared__ char smem[];
    const uint32_t sbase = smem_u32(smem);
    const int tid = threadIdx.x;
    const int wid = tid >> 5, lane = tid & 31;
    const int nt = blockIdx.x;
    const int n0 = nt * 128;
    const int m0 = blockIdx.y * 64;

    const float4* Xf4 = (const float4*)X;
    #pragma unroll 4
    for (int s = tid; s < 2048; s += 256) {
        int row = s >> 5, q = s & 31;
        float4 v = Xf4[(size_t)(m0 + row) * 32 + q];
        __nv_bfloat16 h0, h1, h2, h3, l0, l1, l2, l3;
        split_bf16(v.x, h0, l0); split_bf16(v.y, h1, l1);
        split_bf16(v.z, h2, l2); split_bf16(v.w, h3, l3);
        __nv_bfloat162 hA(h0, h1), hB(h2, h3), lA(l0, l1), lB(l2, l3);
        int off = row * 272 + q * 8;
        *(uint2*)(smem + GSM_AH + off) = make_uint2(*(uint32_t*)&hA, *(uint32_t*)&hB);
        *(uint2*)(smem + GSM_AL + off) = make_uint2(*(uint32_t*)&lA, *(uint32_t*)&lB);
    }
    const uint4* Bh4 = (const uint4*)(g_Bh + nt * 16384);
    const uint4* Bl4 = (const uint4*)(g_Bl + nt * 16384);
    #pragma unroll 4
    for (int s = tid; s < 2048; s += 256) {
        int row = s >> 4, u = s & 15;
        int off = row * 272 + u * 16;
        *(uint4*)(smem + GSM_BH + off) = Bh4[s];
        *(uint4*)(smem + GSM_BL + off) = Bl4[s];
    }
    if (tid < 128) *(float*)(smem + GSM_BC + tid * 4) = g_bc[n0 + tid];
    __syncthreads();

    const int wm = wid & 1;
    const int wn = wid >> 1;
    const uint32_t aoff = (uint32_t)(wm * 32 + (lane & 15)) * 272 + ((lane >> 4) << 4);
    const uint32_t boff = (uint32_t)(wn * 32 + (lane & 7) + ((lane >> 4) << 3)) * 272
                        + (((lane >> 3) & 1) << 4);

    float C[2][4][4];
    #pragma unroll
    for (int mf = 0; mf < 2; mf++)
        #pragma unroll
        for (int nf = 0; nf < 4; nf++)
            #pragma unroll
            for (int q = 0; q < 4; q++) C[mf][nf][q] = 0.f;

    const uint32_t abase[3] = { sbase + GSM_AH, sbase + GSM_AH, sbase + GSM_AL };
    const uint32_t bbase[3] = { sbase + GSM_BH, sbase + GSM_BL, sbase + GSM_BH };

    #pragma unroll
    for (int p = 0; p < 3; p++) {
        const uint32_t ab = abase[p] + aoff;
        const uint32_t bb = bbase[p] + boff;
        #pragma unroll
        for (int ks = 0; ks < 8; ks++) {
            uint32_t a[2][4], b[2][4];
            ldsm4(a[0][0], a[0][1], a[0][2], a[0][3], ab + ks * 32);
            ldsm4(a[1][0], a[1][1], a[1][2], a[1][3], ab + 16 * 272 + ks * 32);
            ldsm4(b[0][0], b[0][1], b[0][2], b[0][3], bb + ks * 32);
            ldsm4(b[1][0], b[1][1], b[1][2], b[1][3], bb + 16 * 272 + ks * 32);
            #pragma unroll
            for (int mf = 0; mf < 2; mf++) {
                mma16816(C[mf][0], a[mf], b[0][0], b[0][1]);
                mma16816(C[mf][1], a[mf], b[0][2], b[0][3]);
                mma16816(C[mf][2], a[mf], b[1][0], b[1][1]);
                mma16816(C[mf][3], a[mf], b[1][2], b[1][3]);
            }
        }
    }

    const float* bcs = (const float*)(smem + GSM_BC);
    const int qrow = lane >> 2, qcol = (lane & 3) * 2;
    #pragma unroll
    for (int mf = 0; mf < 2; mf++) {
        int row = m0 + wm * 32 + mf * 16 + qrow;
        #pragma unroll
        for (int nf = 0; nf < 4; nf++) {
            int colL = wn * 32 + nf * 8 + qcol;
            float b0 = bcs[colL], b1 = bcs[colL + 1];
            float* d0 = g_GI + (size_t)row * GATES + n0 + colL;
            *(float2*)d0 = make_float2(C[mf][nf][0] + b0, C[mf][nf][1] + b1);
            float* d1 = g_GI + (size_t)(row + 8) * GATES + n0 + colL;
            *(float2*)d1 = make_float2(C[mf][nf][2] + b0, C[mf][nf][3] + b1);
        }
    }
}

// ---------------- HMMA GRU scan v4: W_hi in regs, k-split, 512 threads ----------
// 16 warps: kh = w>>3 (k-half), wj = w&7 (j-tile, 16 j's, all 3 gates).
// h buffer [j=k][cols 0-3 hi | 4-7 lo] 16B rows, ping-pong.
// W_lo stays in SMEM (ldsm4 in loop); W_hi fragments preloaded to registers.
// k-halves combined via scratch (kh=1 writes, kh=0 reduces + gates).
#define VW_LO   0                        // 384*272 = 104448 (persistent)
#define VW_HI   104448                   // staging only; overlaid after preload
#define VH      104448                   // h ping-pong: 2 x 2048
#define VSC     (VH + 4096)              // scratch: 12*8*32 floats = 12288
#define VSMEM   (VW_HI + 104448)

__global__ __launch_bounds__(512, 1)
void gru_scan_hmma(const float* __restrict__ W_hh, const float* __restrict__ b_hh,
                   float* __restrict__ out) {
    extern __shared__ char smem[];
    const uint32_t sbase = smem_u32(smem);
    const int tid = threadIdx.x, w = tid >> 5, lane = tid & 31;
    const int kh = w >> 3, wj = w & 7;
    const int r0 = blockIdx.x * 4;

    // stage W_hh -> bf16 hi/lo, 272B-padded rows
    #pragma unroll 4
    for (int s = tid; s < 12288; s += 512) {
        int row = s >> 5, q = s & 31;
        float4 v = ((const float4*)W_hh)[s];
        __nv_bfloat16 h0, h1, h2, h3, l0, l1, l2, l3;
        split_bf16(v.x, h0, l0); split_bf16(v.y, h1, l1);
        split_bf16(v.z, h2, l2); split_bf16(v.w, h3, l3);
        __nv_bfloat162 hA(h0, h1), hB(h2, h3), lA(l0, l1), lB(l2, l3);
        int off = row * 272 + q * 8;
        *(uint2*)(smem + VW_HI + off) = make_uint2(*(uint32_t*)&hA, *(uint32_t*)&hB);
        *(uint2*)(smem + VW_LO + off) = make_uint2(*(uint32_t*)&lA, *(uint32_t*)&lB);
    }
    __syncthreads();

    // preload W_hi fragments: 3 gates x 4 ks (this warp's k-half) = 48 regs
    uint32_t wh[3][4][4];
    {
        const uint32_t ahib = sbase + VW_HI
            + (uint32_t)(16 * wj + (lane & 15)) * 272 + ((lane >> 4) << 4)
            + (uint32_t)kh * 128;
        #pragma unroll
        for (int g = 0; g < 3; g++)
            #pragma unroll
            for (int ks = 0; ks < 4; ks++)
                ldsm4(wh[g][ks][0], wh[g][ks][1], wh[g][ks][2], wh[g][ks][3],
                      ahib + (uint32_t)g * (128 * 272) + ks * 32);
    }
    __syncthreads();   // W_hi region free -> reuse as h + scratch

    // zero h phase 0
    for (int s = tid; s < 512; s += 512)
        ((uint32_t*)(smem + VH))[s] = 0;
    __syncthreads();

    // lane -> (j, b) mapping (same as R7)
    const int jq = lane >> 2;
    const int j0 = 16 * wj + jq, j1 = j0 + 8;
    const int bsel = lane & 3;
    const bool valid = (bsel < 2);
    const int b0 = 2 * bsel;

    const float br0 = b_hh[j0],           br1 = b_hh[j1];
    const float bz0 = b_hh[DIM + j0],     bz1 = b_hh[DIM + j1];
    const float bn0 = b_hh[2 * DIM + j0], bn1 = b_hh[2 * DIM + j1];

    // W_lo ldsm base (this warp's rows + k-half)
    const uint32_t alob = sbase + VW_LO
        + (uint32_t)(16 * wj + (lane & 15)) * 272 + ((lane >> 4) << 4)
        + (uint32_t)kh * 128;
    // B (h) ldsm base: rows = k in this k-half
    const uint32_t bfb = sbase + VH + (uint32_t)((lane & 15) + kh * 64) * 16;
    float* scp = (float*)(smem + VSC);
    const int scidx = wj * 32 + lane;

    float hprev[4] = {0.f, 0.f, 0.f, 0.f};

    for (int t = 0; t < T_STEPS; t++) {
        const int cur = t & 1;

        // prefetch input gates (kh=0 valid lanes)
        float giv[3][4];
        if (kh == 0) {
            #pragma unroll
            for (int q = 0; q < 4; q++) {
                if (valid) {
                    int j = (q & 2) ? j1 : j0;
                    int b = b0 + (q & 1);
                    size_t base = ((size_t)t * BATCH + r0 + b) * GATES + j;
                    giv[0][q] = g_GI[base];
                    giv[1][q] = g_GI[base + DIM];
                    giv[2][q] = g_GI[base + 2 * DIM];
                } else {
                    giv[0][q] = giv[1][q] = giv[2][q] = 0.f;
                }
            }
        }

        // B frags for this k-half (cols 0-3 h_hi, 4-7 h_lo)
        uint32_t bf[4][2];
        {
            const uint32_t hb = bfb + (uint32_t)cur * 2048;
            #pragma unroll
            for (int ks = 0; ks < 4; ks++)
                ldsm2t(bf[ks][0], bf[ks][1], hb + ks * 256);
        }

        float C[3][4];
        #pragma unroll
        for (int g = 0; g < 3; g++)
            #pragma unroll
            for (int q = 0; q < 4; q++) C[g][q] = 0.f;

        // pass 1: W_hi (registers)
        #pragma unroll
        for (int g = 0; g < 3; g++)
            #pragma unroll
            for (int ks = 0; ks < 4; ks++)
                mma16816(C[g], wh[g][ks], bf[ks][0], bf[ks][1]);
        // pass 2: W_lo (SMEM ldsm4)
        #pragma unroll
        for (int g = 0; g < 3; g++) {
            #pragma unroll
            for (int ks = 0; ks < 4; ks++) {
                uint32_t a[4];
                ldsm4(a[0], a[1], a[2], a[3],
                      alob + (uint32_t)g * (128 * 272) + ks * 32);
                mma16816(C[g], a, bf[ks][0], bf[ks][1]);
            }
        }

        // kh=1 publishes partials
        if (kh == 1) {
            #pragma unroll
            for (int g = 0; g < 3; g++)
                #pragma unroll
                for (int q = 0; q < 4; q++)
                    scp[(g * 4 + q) * 256 + scidx] = C[g][q];
        }
        __syncthreads();

        if (kh == 0) {
            // combine k-halves, fold h_lo cols, gates, publish h
            float hnew[4];
            #pragma unroll
            for (int q = 0; q < 4; q++) {
                float gr = C[0][q] + scp[(0 * 4 + q) * 256 + scidx];
                float gz = C[1][q] + scp[(1 * 4 + q) * 256 + scidx];
                float gn = C[2][q] + scp[(2 * 4 + q) * 256 + scidx];
                gr += __shfl_xor_sync(0xffffffffu, gr, 2);
                gz += __shfl_xor_sync(0xffffffffu, gz, 2);
                gn += __shfl_xor_sync(0xffffffffu, gn, 2);
                float br = (q & 2) ? br1 : br0;
                float bz = (q & 2) ? bz1 : bz0;
                float bn = (q & 2) ? bn1 : bn0;
                float r = sigm_fast(gr + br + giv[0][q]);
                float z = sigm_fast(gz + bz + giv[1][q]);
                float n = tanhf_fast(giv[2][q] + r * (gn + bn));
                hnew[q] = n + z * (hprev[q] - n);
                hprev[q] = hnew[q];
            }
            if (valid) {
                const uint32_t nb = VH + (uint32_t)(cur ^ 1) * 2048;
                #pragma unroll
                for (int q = 0; q < 4; q++) {
                    int j = (q & 2) ? j1 : j0;
                    int b = b0 + (q & 1);
                    __nv_bfloat16 hh, hl;
                    split_bf16(hnew[q], hh, hl);
                    *(__nv_bfloat16*)(smem + nb + j * 16 + b * 2) = hh;
                    *(__nv_bfloat16*)(smem + nb + j * 16 + 8 + b * 2) = hl;
                }
            }
        }
        __syncthreads();
    }

    if (kh == 0 && valid) {
        #pragma unroll
        for (int q = 0; q < 4; q++) {
            int j = (q & 2) ? j1 : j0;
            int b = b0 + (q & 1);
            out[(r0 + b) * DIM + j] = hprev[q];
        }
    }
}

// ---------------- launch ----------------
extern "C" void kernel_launch(void* const* d_in, const int* in_sizes, int n_in,
                              void* d_out, int out_size) {
    const float* x    = (const float*)d_in[0];
    const float* W1   = (const float*)d_in[1];
    const float* b1   = (const float*)d_in[2];
    const float* W_ih = (const float*)d_in[3];
    const float* W_hh = (const float*)d_in[4];
    const float* b_ih = (const float*)d_in[5];
    const float* b_hh = (const float*)d_in[6];
    float* out = (float*)d_out;

    static bool attr_done = false;
    if (!attr_done) {
        cudaFuncSetAttribute(gi_gemm_hmma,
                             cudaFuncAttributeMaxDynamicSharedMemorySize, GSMEM);
        cudaFuncSetAttribute(gru_scan_hmma,
                             cudaFuncAttributeMaxDynamicSharedMemorySize, VSMEM);
        attr_done = true;
    }

    prep_kernel<<<GATES, DIM>>>(W1, b1, W_ih, b_ih);
    gi_gemm_hmma<<<dim3(3, 8192), 256, GSMEM>>>(x);
    gru_scan_hmma<<<128, 512, VSMEM>>>(W_hh, b_hh, out);
}

// round 10
// speedup vs baseline: 1.6075x; 1.0204x over previous
#include <cuda_runtime.h>
#include <cuda_bf16.h>
#include <cstdint>

#define T_STEPS 1024
#define BATCH   512
#define DIM     128
#define GATES   384

// ---------------- device scratch ----------------
__device__ float g_bc[GATES];
__device__ __nv_bfloat16 g_Bh[3 * 16384];                // Wc hi: [nt][row][k]
__device__ __nv_bfloat16 g_Bl[3 * 16384];                // Wc lo
__device__ float g_GI[(size_t)T_STEPS * BATCH * GATES];  // 805 MB scratch

// ---------------- helpers ----------------
__device__ __forceinline__ float tanhf_fast(float x) {
    float y; asm("tanh.approx.f32 %0, %1;" : "=f"(y) : "f"(x)); return y;
}
__device__ __forceinline__ float sigm_fast(float x) {
    return fmaf(0.5f, tanhf_fast(0.5f * x), 0.5f);
}
__device__ __forceinline__ uint32_t smem_u32(const void* p) {
    uint32_t a;
    asm("{ .reg .u64 t; cvta.to.shared.u64 t, %1; cvt.u32.u64 %0, t; }" : "=r"(a) : "l"(p));
    return a;
}
__device__ __forceinline__ void ldsm4(uint32_t& r0, uint32_t& r1, uint32_t& r2, uint32_t& r3,
                                      uint32_t addr) {
    asm volatile("ldmatrix.sync.aligned.m8n8.x4.shared.b16 {%0,%1,%2,%3}, [%4];"
                 : "=r"(r0), "=r"(r1), "=r"(r2), "=r"(r3) : "r"(addr));
}
__device__ __forceinline__ void ldsm2t(uint32_t& r0, uint32_t& r1, uint32_t addr) {
    asm volatile("ldmatrix.sync.aligned.m8n8.x2.trans.shared.b16 {%0,%1}, [%2];"
                 : "=r"(r0), "=r"(r1) : "r"(addr));
}
__device__ __forceinline__ void mma16816(float* c, const uint32_t* a, uint32_t b0, uint32_t b1) {
    asm volatile(
        "mma.sync.aligned.m16n8k16.row.col.f32.bf16.bf16.f32 "
        "{%0,%1,%2,%3}, {%4,%5,%6,%7}, {%8,%9}, {%0,%1,%2,%3};"
        : "+f"(c[0]), "+f"(c[1]), "+f"(c[2]), "+f"(c[3])
        : "r"(a[0]), "r"(a[1]), "r"(a[2]), "r"(a[3]), "r"(b0), "r"(b1));
}
__device__ __forceinline__ void split_bf16(float v, __nv_bfloat16& h, __nv_bfloat16& l) {
    h = __float2bfloat16(v);
    l = __float2bfloat16(v - __bfloat162float(h));
}

// ---------------- prep ----------------
__global__ void prep_kernel(const float* __restrict__ W1, const float* __restrict__ b1,
                            const float* __restrict__ W_ih, const float* __restrict__ b_ih) {
    int bid = blockIdx.x, tid = threadIdx.x;
    __shared__ float wih[DIM];
    __shared__ float red[DIM];
    wih[tid] = W_ih[bid * DIM + tid];
    __syncthreads();
    float acc = 0.f;
    #pragma unroll 8
    for (int k = 0; k < DIM; k++)
        acc = fmaf(wih[k], W1[k * DIM + tid], acc);
    __nv_bfloat16 h, l;
    split_bf16(acc, h, l);
    g_Bh[bid * DIM + tid] = h;
    g_Bl[bid * DIM + tid] = l;
    red[tid] = wih[tid] * b1[tid];
    __syncthreads();
    if (tid == 0) {
        float s = 0.f;
        for (int k = 0; k < DIM; k++) s += red[k];
        g_bc[bid] = s + b_ih[bid];
    }
}

// ---------------- HMMA GI GEMM (unchanged, occ 2) ----------------
#define GSM_BC  0
#define GSM_AH  1024
#define GSM_AL  (GSM_AH + 64 * 272)
#define GSM_BH  (GSM_AL + 64 * 272)
#define GSM_BL  (GSM_BH + 128 * 272)
#define GSMEM   (GSM_BL + 128 * 272)

__global__ __launch_bounds__(256, 2)
void gi_gemm_hmma(const float* __restrict__ X) {
    extern __shared__ char smem[];
    const uint32_t sbase = smem_u32(smem);
    const int tid = threadIdx.x;
    const int wid = tid >> 5, lane = tid & 31;
    const int nt = blockIdx.x;
    const int n0 = nt * 128;
    const int m0 = blockIdx.y * 64;

    const float4* Xf4 = (const float4*)X;
    #pragma unroll 4
    for (int s = tid; s < 2048; s += 256) {
        int row = s >> 5, q = s & 31;
        float4 v = Xf4[(size_t)(m0 + row) * 32 + q];
        __nv_bfloat16 h0, h1, h2, h3, l0, l1, l2, l3;
        split_bf16(v.x, h0, l0); split_bf16(v.y, h1, l1);
        split_bf16(v.z, h2, l2); split_bf16(v.w, h3, l3);
        __nv_bfloat162 hA(h0, h1), hB(h2, h3), lA(l0, l1), lB(l2, l3);
        int off = row * 272 + q * 8;
        *(uint2*)(smem + GSM_AH + off) = make_uint2(*(uint32_t*)&hA, *(uint32_t*)&hB);
        *(uint2*)(smem + GSM_AL + off) = make_uint2(*(uint32_t*)&lA, *(uint32_t*)&lB);
    }
    const uint4* Bh4 = (const uint4*)(g_Bh + nt * 16384);
    const uint4* Bl4 = (const uint4*)(g_Bl + nt * 16384);
    #pragma unroll 4
    for (int s = tid; s < 2048; s += 256) {
        int row = s >> 4, u = s & 15;
        int off = row * 272 + u * 16;
        *(uint4*)(smem + GSM_BH + off) = Bh4[s];
        *(uint4*)(smem + GSM_BL + off) = Bl4[s];
    }
    if (tid < 128) *(float*)(smem + GSM_BC + tid * 4) = g_bc[n0 + tid];
    __syncthreads();

    const int wm = wid & 1;
    const int wn = wid >> 1;
    const uint32_t aoff = (uint32_t)(wm * 32 + (lane & 15)) * 272 + ((lane >> 4) << 4);
    const uint32_t boff = (uint32_t)(wn * 32 + (lane & 7) + ((lane >> 4) << 3)) * 272
                        + (((lane >> 3) & 1) << 4);

    float C[2][4][4];
    #pragma unroll
    for (int mf = 0; mf < 2; mf++)
        #pragma unroll
        for (int nf = 0; nf < 4; nf++)
            #pragma unroll
            for (int q = 0; q < 4; q++) C[mf][nf][q] = 0.f;

    const uint32_t abase[3] = { sbase + GSM_AH, sbase + GSM_AH, sbase + GSM_AL };
    const uint32_t bbase[3] = { sbase + GSM_BH, sbase + GSM_BL, sbase + GSM_BH };

    #pragma unroll
    for (int p = 0; p < 3; p++) {
        const uint32_t ab = abase[p] + aoff;
        const uint32_t bb = bbase[p] + boff;
        #pragma unroll
        for (int ks = 0; ks < 8; ks++) {
            uint32_t a[2][4], b[2][4];
            ldsm4(a[0][0], a[0][1], a[0][2], a[0][3], ab + ks * 32);
            ldsm4(a[1][0], a[1][1], a[1][2], a[1][3], ab + 16 * 272 + ks * 32);
            ldsm4(b[0][0], b[0][1], b[0][2], b[0][3], bb + ks * 32);
            ldsm4(b[1][0], b[1][1], b[1][2], b[1][3], bb + 16 * 272 + ks * 32);
            #pragma unroll
            for (int mf = 0; mf < 2; mf++) {
                mma16816(C[mf][0], a[mf], b[0][0], b[0][1]);
                mma16816(C[mf][1], a[mf], b[0][2], b[0][3]);
                mma16816(C[mf][2], a[mf], b[1][0], b[1][1]);
                mma16816(C[mf][3], a[mf], b[1][2], b[1][3]);
            }
        }
    }

    const float* bcs = (const float*)(smem + GSM_BC);
    const int qrow = lane >> 2, qcol = (lane & 3) * 2;
    #pragma unroll
    for (int mf = 0; mf < 2; mf++) {
        int row = m0 + wm * 32 + mf * 16 + qrow;
        #pragma unroll
        for (int nf = 0; nf < 4; nf++) {
            int colL = wn * 32 + nf * 8 + qcol;
            float b0 = bcs[colL], b1 = bcs[colL + 1];
            float* d0 = g_GI + (size_t)row * GATES + n0 + colL;
            *(float2*)d0 = make_float2(C[mf][nf][0] + b0, C[mf][nf][1] + b1);
            float* d1 = g_GI + (size_t)(row + 8) * GATES + n0 + colL;
            *(float2*)d1 = make_float2(C[mf][nf][2] + b0, C[mf][nf][3] + b1);
        }
    }
}

// ---------------- HMMA GRU scan v5: W_hi in regs, full k per warp, 1 barrier ----
// 256 threads, 8 warps; warp w owns j in [16w,16w+16) for all 3 gates, full k.
// W_hi fragments (3g x 8ks x 4) = 96 regs/thread; W_lo ldsm4 in loop.
// B frag = [k][cols 0-3 h_hi | 4-7 h_lo], ping-pong; ONE __syncthreads per step.
#define VW_LO   0                        // 384*272 = 104448 (persistent)
#define VW_HI   104448                   // staging; overlaid by h after preload
#define VH      104448                   // h ping-pong: 2 x 2048
#define VSMEM   (104448 * 2)

__global__ __launch_bounds__(256, 1)
void gru_scan_hmma(const float* __restrict__ W_hh, const float* __restrict__ b_hh,
                   float* __restrict__ out) {
    extern __shared__ char smem[];
    const uint32_t sbase = smem_u32(smem);
    const int tid = threadIdx.x, w = tid >> 5, lane = tid & 31;
    const int r0 = blockIdx.x * 4;

    // stage W_hh -> bf16 hi/lo, 272B-padded rows
    #pragma unroll 4
    for (int s = tid; s < 12288; s += 256) {
        int row = s >> 5, q = s & 31;
        float4 v = ((const float4*)W_hh)[s];
        __nv_bfloat16 h0, h1, h2, h3, l0, l1, l2, l3;
        split_bf16(v.x, h0, l0); split_bf16(v.y, h1, l1);
        split_bf16(v.z, h2, l2); split_bf16(v.w, h3, l3);
        __nv_bfloat162 hA(h0, h1), hB(h2, h3), lA(l0, l1), lB(l2, l3);
        int off = row * 272 + q * 8;
        *(uint2*)(smem + VW_HI + off) = make_uint2(*(uint32_t*)&hA, *(uint32_t*)&hB);
        *(uint2*)(smem + VW_LO + off) = make_uint2(*(uint32_t*)&lA, *(uint32_t*)&lB);
    }
    __syncthreads();

    // preload W_hi fragments: 3 gates x 8 ks = 96 regs
    uint32_t wh[3][8][4];
    {
        const uint32_t ahib = sbase + VW_HI
            + (uint32_t)(16 * w + (lane & 15)) * 272 + ((lane >> 4) << 4);
        #pragma unroll
        for (int g = 0; g < 3; g++)
            #pragma unroll
            for (int ks = 0; ks < 8; ks++)
                ldsm4(wh[g][ks][0], wh[g][ks][1], wh[g][ks][2], wh[g][ks][3],
                      ahib + (uint32_t)g * (128 * 272) + ks * 32);
    }
    __syncthreads();   // W_hi region free -> reuse as h ping-pong

    // zero h phase 0
    for (int s = tid; s < 512; s += 256)
        ((uint32_t*)(smem + VH))[s] = 0;
    __syncthreads();

    // lane -> (j, b) mapping
    const int jq = lane >> 2;
    const int j0 = 16 * w + jq, j1 = j0 + 8;
    const int bsel = lane & 3;
    const bool valid = (bsel < 2);
    const int b0 = 2 * bsel;

    const float br0 = b_hh[j0],           br1 = b_hh[j1];
    const float bz0 = b_hh[DIM + j0],     bz1 = b_hh[DIM + j1];
    const float bn0 = b_hh[2 * DIM + j0], bn1 = b_hh[2 * DIM + j1];

    const uint32_t alob = sbase + VW_LO
        + (uint32_t)(16 * w + (lane & 15)) * 272 + ((lane >> 4) << 4);
    const uint32_t bfb = sbase + VH + (uint32_t)(lane & 15) * 16;

    float hprev[4] = {0.f, 0.f, 0.f, 0.f};

    for (int t = 0; t < T_STEPS; t++) {
        const int cur = t & 1;

        // prefetch input gates (valid lanes; consumed post-mma -> latency hidden)
        float giv[3][4];
        #pragma unroll
        for (int q = 0; q < 4; q++) {
            if (valid) {
                int j = (q & 2) ? j1 : j0;
                int b = b0 + (q & 1);
                size_t base = ((size_t)t * BATCH + r0 + b) * GATES + j;
                giv[0][q] = g_GI[base];
                giv[1][q] = g_GI[base + DIM];
                giv[2][q] = g_GI[base + 2 * DIM];
            } else {
                giv[0][q] = giv[1][q] = giv[2][q] = 0.f;
            }
        }

        // B frags (cols 0-3 h_hi, 4-7 h_lo)
        uint32_t bf[8][2];
        {
            const uint32_t hb = bfb + (uint32_t)cur * 2048;
            #pragma unroll
            for (int ks = 0; ks < 8; ks++)
                ldsm2t(bf[ks][0], bf[ks][1], hb + ks * 256);
        }

        float C[3][4];
        #pragma unroll
        for (int g = 0; g < 3; g++)
            #pragma unroll
            for (int q = 0; q < 4; q++) C[g][q] = 0.f;

        // ks-outer, gate-inner: adjacent mma hit different accumulators
        #pragma unroll
        for (int ks = 0; ks < 8; ks++) {
            uint32_t al[3][4];
            #pragma unroll
            for (int g = 0; g < 3; g++)
                ldsm4(al[g][0], al[g][1], al[g][2], al[g][3],
                      alob + (uint32_t)g * (128 * 272) + ks * 32);
            #pragma unroll
            for (int g = 0; g < 3; g++)
                mma16816(C[g], wh[g][ks], bf[ks][0], bf[ks][1]);
            #pragma unroll
            for (int g = 0; g < 3; g++)
                mma16816(C[g], al[g], bf[ks][0], bf[ks][1]);
        }

        // fold h_lo columns, gates, publish h
        float hnew[4];
        #pragma unroll
        for (int q = 0; q < 4; q++) {
            float gr = C[0][q]; gr += __shfl_xor_sync(0xffffffffu, gr, 2);
            float gz = C[1][q]; gz += __shfl_xor_sync(0xffffffffu, gz, 2);
            float gn = C[2][q]; gn += __shfl_xor_sync(0xffffffffu, gn, 2);
            float br = (q & 2) ? br1 : br0;
            float bz = (q & 2) ? bz1 : bz0;
            float bn = (q & 2) ? bn1 : bn0;
            float r = sigm_fast(gr + br + giv[0][q]);
            float z = sigm_fast(gz + bz + giv[1][q]);
            float n = tanhf_fast(giv[2][q] + r * (gn + bn));
            hnew[q] = n + z * (hprev[q] - n);
            hprev[q] = hnew[q];
        }
        if (valid) {
            const uint32_t nb = VH + (uint32_t)(cur ^ 1) * 2048;
            #pragma unroll
            for (int q = 0; q < 4; q++) {
                int j = (q & 2) ? j1 : j0;
                int b = b0 + (q & 1);
                __nv_bfloat16 hh, hl;
                split_bf16(hnew[q], hh, hl);
                *(__nv_bfloat16*)(smem + nb + j * 16 + b * 2) = hh;
                *(__nv_bfloat16*)(smem + nb + j * 16 + 8 + b * 2) = hl;
            }
        }
        __syncthreads();
    }

    if (valid) {
        #pragma unroll
        for (int q = 0; q < 4; q++) {
            int j = (q & 2) ? j1 : j0;
            int b = b0 + (q & 1);
            out[(r0 + b) * DIM + j] = hprev[q];
        }
    }
}

// ---------------- launch ----------------
extern "C" void kernel_launch(void* const* d_in, const int* in_sizes, int n_in,
                              void* d_out, int out_size) {
    const float* x    = (const float*)d_in[0];
    const float* W1   = (const float*)d_in[1];
    const float* b1   = (const float*)d_in[2];
    const float* W_ih = (const float*)d_in[3];
    const float* W_hh = (const float*)d_in[4];
    const float* b_ih = (const float*)d_in[5];
    const float* b_hh = (const float*)d_in[6];
    float* out = (float*)d_out;

    static bool attr_done = false;
    if (!attr_done) {
        cudaFuncSetAttribute(gi_gemm_hmma,
                             cudaFuncAttributeMaxDynamicSharedMemorySize, GSMEM);
        cudaFuncSetAttribute(gru_scan_hmma,
                             cudaFuncAttributeMaxDynamicSharedMemorySize, VSMEM);
        attr_done = true;
    }

    prep_kernel<<<GATES, DIM>>>(W1, b1, W_ih, b_ih);
    gi_gemm_hmma<<<dim3(3, 8192), 256, GSMEM>>>(x);
    gru_scan_hmma<<<128, 256, VSMEM>>>(W_hh, b_hh, out);
}

// round 11
// speedup vs baseline: 1.6635x; 1.0349x over previous
#include <cuda_runtime.h>
#include <cuda_bf16.h>
#include <cstdint>

#define T_STEPS 1024
#define BATCH   512
#define DIM     128
#define GATES   384

// ---------------- device scratch ----------------
__device__ float g_bc[GATES];
__device__ __nv_bfloat16 g_Bh[3 * 16384];                // Wc hi: [nt][row][k]
__device__ __nv_bfloat16 g_Bl[3 * 16384];                // Wc lo
__device__ float g_GI[(size_t)T_STEPS * BATCH * GATES];  // 805 MB scratch

// ---------------- helpers ----------------
__device__ __forceinline__ float tanhf_fast(float x) {
    float y; asm("tanh.approx.f32 %0, %1;" : "=f"(y) : "f"(x)); return y;
}
__device__ __forceinline__ float sigm_fast(float x) {
    return fmaf(0.5f, tanhf_fast(0.5f * x), 0.5f);
}
__device__ __forceinline__ uint32_t smem_u32(const void* p) {
    uint32_t a;
    asm("{ .reg .u64 t; cvta.to.shared.u64 t, %1; cvt.u32.u64 %0, t; }" : "=r"(a) : "l"(p));
    return a;
}
__device__ __forceinline__ void ldsm4(uint32_t& r0, uint32_t& r1, uint32_t& r2, uint32_t& r3,
                                      uint32_t addr) {
    asm volatile("ldmatrix.sync.aligned.m8n8.x4.shared.b16 {%0,%1,%2,%3}, [%4];"
                 : "=r"(r0), "=r"(r1), "=r"(r2), "=r"(r3) : "r"(addr));
}
__device__ __forceinline__ void ldsm2t(uint32_t& r0, uint32_t& r1, uint32_t addr) {
    asm volatile("ldmatrix.sync.aligned.m8n8.x2.trans.shared.b16 {%0,%1}, [%2];"
                 : "=r"(r0), "=r"(r1) : "r"(addr));
}
__device__ __forceinline__ void mma16816(float* c, const uint32_t* a, uint32_t b0, uint32_t b1) {
    asm volatile(
        "mma.sync.aligned.m16n8k16.row.col.f32.bf16.bf16.f32 "
        "{%0,%1,%2,%3}, {%4,%5,%6,%7}, {%8,%9}, {%0,%1,%2,%3};"
        : "+f"(c[0]), "+f"(c[1]), "+f"(c[2]), "+f"(c[3])
        : "r"(a[0]), "r"(a[1]), "r"(a[2]), "r"(a[3]), "r"(b0), "r"(b1));
}
__device__ __forceinline__ void split_bf16(float v, __nv_bfloat16& h, __nv_bfloat16& l) {
    h = __float2bfloat16(v);
    l = __float2bfloat16(v - __bfloat162float(h));
}

// ---------------- prep ----------------
__global__ void prep_kernel(const float* __restrict__ W1, const float* __restrict__ b1,
                            const float* __restrict__ W_ih, const float* __restrict__ b_ih) {
    int bid = blockIdx.x, tid = threadIdx.x;
    __shared__ float wih[DIM];
    __shared__ float red[DIM];
    wih[tid] = W_ih[bid * DIM + tid];
    __syncthreads();
    float acc = 0.f;
    #pragma unroll 8
    for (int k = 0; k < DIM; k++)
        acc = fmaf(wih[k], W1[k * DIM + tid], acc);
    __nv_bfloat16 h, l;
    split_bf16(acc, h, l);
    g_Bh[bid * DIM + tid] = h;
    g_Bl[bid * DIM + tid] = l;
    red[tid] = wih[tid] * b1[tid];
    __syncthreads();
    if (tid == 0) {
        float s = 0.f;
        for (int k = 0; k < DIM; k++) s += red[k];
        g_bc[bid] = s + b_ih[bid];
    }
}

// ---------------- HMMA GI GEMM (unchanged, occ 2) ----------------
#define GSM_BC  0
#define GSM_AH  1024
#define GSM_AL  (GSM_AH + 64 * 272)
#define GSM_BH  (GSM_AL + 64 * 272)
#define GSM_BL  (GSM_BH + 128 * 272)
#define GSMEM   (GSM_BL + 128 * 272)

__global__ __launch_bounds__(256, 2)
void gi_gemm_hmma(const float* __restrict__ X) {
    extern __shared__ char smem[];
    const uint32_t sbase = smem_u32(smem);
    const int tid = threadIdx.x;
    const int wid = tid >> 5, lane = tid & 31;
    const int nt = blockIdx.x;
    const int n0 = nt * 128;
    const int m0 = blockIdx.y * 64;

    const float4* Xf4 = (const float4*)X;
    #pragma unroll 4
    for (int s = tid; s < 2048; s += 256) {
        int row = s >> 5, q = s & 31;
        float4 v = Xf4[(size_t)(m0 + row) * 32 + q];
        __nv_bfloat16 h0, h1, h2, h3, l0, l1, l2, l3;
        split_bf16(v.x, h0, l0); split_bf16(v.y, h1, l1);
        split_bf16(v.z, h2, l2); split_bf16(v.w, h3, l3);
        __nv_bfloat162 hA(h0, h1), hB(h2, h3), lA(l0, l1), lB(l2, l3);
        int off = row * 272 + q * 8;
        *(uint2*)(smem + GSM_AH + off) = make_uint2(*(uint32_t*)&hA, *(uint32_t*)&hB);
        *(uint2*)(smem + GSM_AL + off) = make_uint2(*(uint32_t*)&lA, *(uint32_t*)&lB);
    }
    const uint4* Bh4 = (const uint4*)(g_Bh + nt * 16384);
    const uint4* Bl4 = (const uint4*)(g_Bl + nt * 16384);
    #pragma unroll 4
    for (int s = tid; s < 2048; s += 256) {
        int row = s >> 4, u = s & 15;
        int off = row * 272 + u * 16;
        *(uint4*)(smem + GSM_BH + off) = Bh4[s];
        *(uint4*)(smem + GSM_BL + off) = Bl4[s];
    }
    if (tid < 128) *(float*)(smem + GSM_BC + tid * 4) = g_bc[n0 + tid];
    __syncthreads();

    const int wm = wid & 1;
    const int wn = wid >> 1;
    const uint32_t aoff = (uint32_t)(wm * 32 + (lane & 15)) * 272 + ((lane >> 4) << 4);
    const uint32_t boff = (uint32_t)(wn * 32 + (lane & 7) + ((lane >> 4) << 3)) * 272
                        + (((lane >> 3) & 1) << 4);

    float C[2][4][4];
    #pragma unroll
    for (int mf = 0; mf < 2; mf++)
        #pragma unroll
        for (int nf = 0; nf < 4; nf++)
            #pragma unroll
            for (int q = 0; q < 4; q++) C[mf][nf][q] = 0.f;

    const uint32_t abase[3] = { sbase + GSM_AH, sbase + GSM_AH, sbase + GSM_AL };
    const uint32_t bbase[3] = { sbase + GSM_BH, sbase + GSM_BL, sbase + GSM_BH };

    #pragma unroll
    for (int p = 0; p < 3; p++) {
        const uint32_t ab = abase[p] + aoff;
        const uint32_t bb = bbase[p] + boff;
        #pragma unroll
        for (int ks = 0; ks < 8; ks++) {
            uint32_t a[2][4], b[2][4];
            ldsm4(a[0][0], a[0][1], a[0][2], a[0][3], ab + ks * 32);
            ldsm4(a[1][0], a[1][1], a[1][2], a[1][3], ab + 16 * 272 + ks * 32);
            ldsm4(b[0][0], b[0][1], b[0][2], b[0][3], bb + ks * 32);
            ldsm4(b[1][0], b[1][1], b[1][2], b[1][3], bb + 16 * 272 + ks * 32);
            #pragma unroll
            for (int mf = 0; mf < 2; mf++) {
                mma16816(C[mf][0], a[mf], b[0][0], b[0][1]);
                mma16816(C[mf][1], a[mf], b[0][2], b[0][3]);
                mma16816(C[mf][2], a[mf], b[1][0], b[1][1]);
                mma16816(C[mf][3], a[mf], b[1][2], b[1][3]);
            }
        }
    }

    const float* bcs = (const float*)(smem + GSM_BC);
    const int qrow = lane >> 2, qcol = (lane & 3) * 2;
    #pragma unroll
    for (int mf = 0; mf < 2; mf++) {
        int row = m0 + wm * 32 + mf * 16 + qrow;
        #pragma unroll
        for (int nf = 0; nf < 4; nf++) {
            int colL = wn * 32 + nf * 8 + qcol;
            float b0 = bcs[colL], b1 = bcs[colL + 1];
            float* d0 = g_GI + (size_t)row * GATES + n0 + colL;
            *(float2*)d0 = make_float2(C[mf][nf][0] + b0, C[mf][nf][1] + b1);
            float* d1 = g_GI + (size_t)(row + 8) * GATES + n0 + colL;
            *(float2*)d1 = make_float2(C[mf][nf][2] + b0, C[mf][nf][3] + b1);
        }
    }
}

// ---------------- HMMA GRU scan v6: ALL W fragments in registers ----------------
// 256 threads, 8 warps; warp w owns j in [16w,16w+16) for all 3 gates, full k.
// W_hi + W_lo fragments = 192 regs/thread; zero W crossbar traffic in loop.
// B frag ks-outer with 2-reg double buffer; ONE __syncthreads per step.
#define VW_LO   0                        // staging 384*272 = 104448
#define VW_HI   104448                   // staging 104448
#define VH      0                        // h ping-pong (reuses staging): 2 x 2048
#define VSMEM   (104448 * 2)

__global__ __launch_bounds__(256, 1)
void gru_scan_hmma(const float* __restrict__ W_hh, const float* __restrict__ b_hh,
                   float* __restrict__ out) {
    extern __shared__ char smem[];
    const uint32_t sbase = smem_u32(smem);
    const int tid = threadIdx.x, w = tid >> 5, lane = tid & 31;
    const int r0 = blockIdx.x * 4;

    // stage W_hh -> bf16 hi/lo, 272B-padded rows
    #pragma unroll 4
    for (int s = tid; s < 12288; s += 256) {
        int row = s >> 5, q = s & 31;
        float4 v = ((const float4*)W_hh)[s];
        __nv_bfloat16 h0, h1, h2, h3, l0, l1, l2, l3;
        split_bf16(v.x, h0, l0); split_bf16(v.y, h1, l1);
        split_bf16(v.z, h2, l2); split_bf16(v.w, h3, l3);
        __nv_bfloat162 hA(h0, h1), hB(h2, h3), lA(l0, l1), lB(l2, l3);
        int off = row * 272 + q * 8;
        *(uint2*)(smem + VW_HI + off) = make_uint2(*(uint32_t*)&hA, *(uint32_t*)&hB);
        *(uint2*)(smem + VW_LO + off) = make_uint2(*(uint32_t*)&lA, *(uint32_t*)&lB);
    }
    __syncthreads();

    // preload ALL W fragments: (hi + lo) x 3 gates x 8 ks = 192 regs
    uint32_t wh[3][8][4], wl[3][8][4];
    {
        const uint32_t lo_off = (uint32_t)(16 * w + (lane & 15)) * 272 + ((lane >> 4) << 4);
        #pragma unroll
        for (int g = 0; g < 3; g++)
            #pragma unroll
            for (int ks = 0; ks < 8; ks++) {
                ldsm4(wh[g][ks][0], wh[g][ks][1], wh[g][ks][2], wh[g][ks][3],
                      sbase + VW_HI + lo_off + (uint32_t)g * (128 * 272) + ks * 32);
                ldsm4(wl[g][ks][0], wl[g][ks][1], wl[g][ks][2], wl[g][ks][3],
                      sbase + VW_LO + lo_off + (uint32_t)g * (128 * 272) + ks * 32);
            }
    }
    __syncthreads();   // all staging reads done -> reuse region for h ping-pong

    // zero h phase 0
    for (int s = tid; s < 512; s += 256)
        ((uint32_t*)(smem + VH))[s] = 0;
    __syncthreads();

    // lane -> (j, b) mapping
    const int jq = lane >> 2;
    const int j0 = 16 * w + jq, j1 = j0 + 8;
    const int bsel = lane & 3;
    const bool valid = (bsel < 2);
    const int b0 = 2 * bsel;

    const float br0 = b_hh[j0],           br1 = b_hh[j1];
    const float bz0 = b_hh[DIM + j0],     bz1 = b_hh[DIM + j1];
    const float bn0 = b_hh[2 * DIM + j0], bn1 = b_hh[2 * DIM + j1];

    const uint32_t bfb = sbase + VH + (uint32_t)(lane & 15) * 16;

    float hprev[4] = {0.f, 0.f, 0.f, 0.f};

    for (int t = 0; t < T_STEPS; t++) {
        const int cur = t & 1;

        // prefetch input gates (valid lanes; consumed post-mma -> latency hidden)
        float giv[3][4];
        #pragma unroll
        for (int q = 0; q < 4; q++) {
            if (valid) {
                int j = (q & 2) ? j1 : j0;
                int b = b0 + (q & 1);
                size_t base = ((size_t)t * BATCH + r0 + b) * GATES + j;
                giv[0][q] = g_GI[base];
                giv[1][q] = g_GI[base + DIM];
                giv[2][q] = g_GI[base + 2 * DIM];
            } else {
                giv[0][q] = giv[1][q] = giv[2][q] = 0.f;
            }
        }

        float C[3][4];
        #pragma unroll
        for (int g = 0; g < 3; g++)
            #pragma unroll
            for (int q = 0; q < 4; q++) C[g][q] = 0.f;

        // ks-outer; B frag double-buffered (2+2 live regs), 6 mma per ks
        const uint32_t hb = bfb + (uint32_t)cur * 2048;
        uint32_t bf0, bf1;
        ldsm2t(bf0, bf1, hb);
        #pragma unroll
        for (int ks = 0; ks < 8; ks++) {
            uint32_t nf0 = 0, nf1 = 0;
            if (ks < 7) ldsm2t(nf0, nf1, hb + (ks + 1) * 256);
            mma16816(C[0], wh[0][ks], bf0, bf1);
            mma16816(C[1], wh[1][ks], bf0, bf1);
            mma16816(C[2], wh[2][ks], bf0, bf1);
            mma16816(C[0], wl[0][ks], bf0, bf1);
            mma16816(C[1], wl[1][ks], bf0, bf1);
            mma16816(C[2], wl[2][ks], bf0, bf1);
            bf0 = nf0; bf1 = nf1;
        }

        // fold h_lo columns, gates, publish h
        float hnew[4];
        #pragma unroll
        for (int q = 0; q < 4; q++) {
            float gr = C[0][q]; gr += __shfl_xor_sync(0xffffffffu, gr, 2);
            float gz = C[1][q]; gz += __shfl_xor_sync(0xffffffffu, gz, 2);
            float gn = C[2][q]; gn += __shfl_xor_sync(0xffffffffu, gn, 2);
            float br = (q & 2) ? br1 : br0;
            float bz = (q & 2) ? bz1 : bz0;
            float bn = (q & 2) ? bn1 : bn0;
            float r = sigm_fast(gr + br + giv[0][q]);
            float z = sigm_fast(gz + bz + giv[1][q]);
            float n = tanhf_fast(giv[2][q] + r * (gn + bn));
            hnew[q] = n + z * (hprev[q] - n);
            hprev[q] = hnew[q];
        }
        if (valid) {
            const uint32_t nb = VH + (uint32_t)(cur ^ 1) * 2048;
            #pragma unroll
            for (int q = 0; q < 4; q++) {
                int j = (q & 2) ? j1 : j0;
                int b = b0 + (q & 1);
                __nv_bfloat16 hh, hl;
                split_bf16(hnew[q], hh, hl);
                *(__nv_bfloat16*)(smem + nb + j * 16 + b * 2) = hh;
                *(__nv_bfloat16*)(smem + nb + j * 16 + 8 + b * 2) = hl;
            }
        }
        __syncthreads();
    }

    if (valid) {
        #pragma unroll
        for (int q = 0; q < 4; q++) {
            int j = (q & 2) ? j1 : j0;
            int b = b0 + (q & 1);
            out[(r0 + b) * DIM + j] = hprev[q];
        }
    }
}

// ---------------- launch ----------------
extern "C" void kernel_launch(void* const* d_in, const int* in_sizes, int n_in,
                              void* d_out, int out_size) {
    const float* x    = (const float*)d_in[0];
    const float* W1   = (const float*)d_in[1];
    const float* b1   = (const float*)d_in[2];
    const float* W_ih = (const float*)d_in[3];
    const float* W_hh = (const float*)d_in[4];
    const float* b_ih = (const float*)d_in[5];
    const float* b_hh = (const float*)d_in[6];
    float* out = (float*)d_out;

    static bool attr_done = false;
    if (!attr_done) {
        cudaFuncSetAttribute(gi_gemm_hmma,
                             cudaFuncAttributeMaxDynamicSharedMemorySize, GSMEM);
        cudaFuncSetAttribute(gru_scan_hmma,
                             cudaFuncAttributeMaxDynamicSharedMemorySize, VSMEM);
        attr_done = true;
    }

    prep_kernel<<<GATES, DIM>>>(W1, b1, W_ih, b_ih);
    gi_gemm_hmma<<<dim3(3, 8192), 256, GSMEM>>>(x);
    gru_scan_hmma<<<128, 256, VSMEM>>>(W_hh, b_hh, out);
}

// round 12
// speedup vs baseline: 1.7163x; 1.0317x over previous
#include <cuda_runtime.h>
#include <cuda_bf16.h>
#include <cstdint>

#define T_STEPS 1024
#define BATCH   512
#define DIM     128
#define GATES   384

// ---------------- device scratch ----------------
__device__ float g_bc[GATES];
__device__ __nv_bfloat16 g_Bh[3 * 16384];                // Wc hi: [nt][row][k]
__device__ __nv_bfloat16 g_Bl[3 * 16384];                // Wc lo
__device__ float g_GI[(size_t)T_STEPS * BATCH * GATES];  // 805 MB scratch

// ---------------- helpers ----------------
__device__ __forceinline__ float tanhf_fast(float x) {
    float y; asm("tanh.approx.f32 %0, %1;" : "=f"(y) : "f"(x)); return y;
}
__device__ __forceinline__ float sigm_fast(float x) {
    return fmaf(0.5f, tanhf_fast(0.5f * x), 0.5f);
}
__device__ __forceinline__ uint32_t smem_u32(const void* p) {
    uint32_t a;
    asm("{ .reg .u64 t; cvta.to.shared.u64 t, %1; cvt.u32.u64 %0, t; }" : "=r"(a) : "l"(p));
    return a;
}
__device__ __forceinline__ void ldsm4(uint32_t& r0, uint32_t& r1, uint32_t& r2, uint32_t& r3,
                                      uint32_t addr) {
    asm volatile("ldmatrix.sync.aligned.m8n8.x4.shared.b16 {%0,%1,%2,%3}, [%4];"
                 : "=r"(r0), "=r"(r1), "=r"(r2), "=r"(r3) : "r"(addr));
}
__device__ __forceinline__ void ldsm2t(uint32_t& r0, uint32_t& r1, uint32_t addr) {
    asm volatile("ldmatrix.sync.aligned.m8n8.x2.trans.shared.b16 {%0,%1}, [%2];"
                 : "=r"(r0), "=r"(r1) : "r"(addr));
}
__device__ __forceinline__ void mma16816(float* c, const uint32_t* a, uint32_t b0, uint32_t b1) {
    asm volatile(
        "mma.sync.aligned.m16n8k16.row.col.f32.bf16.bf16.f32 "
        "{%0,%1,%2,%3}, {%4,%5,%6,%7}, {%8,%9}, {%0,%1,%2,%3};"
        : "+f"(c[0]), "+f"(c[1]), "+f"(c[2]), "+f"(c[3])
        : "r"(a[0]), "r"(a[1]), "r"(a[2]), "r"(a[3]), "r"(b0), "r"(b1));
}
__device__ __forceinline__ void split_bf16(float v, __nv_bfloat16& h, __nv_bfloat16& l) {
    h = __float2bfloat16(v);
    l = __float2bfloat16(v - __bfloat162float(h));
}

// ---------------- prep ----------------
__global__ void prep_kernel(const float* __restrict__ W1, const float* __restrict__ b1,
                            const float* __restrict__ W_ih, const float* __restrict__ b_ih) {
    int bid = blockIdx.x, tid = threadIdx.x;
    __shared__ float wih[DIM];
    __shared__ float red[DIM];
    wih[tid] = W_ih[bid * DIM + tid];
    __syncthreads();
    float acc = 0.f;
    #pragma unroll 8
    for (int k = 0; k < DIM; k++)
        acc = fmaf(wih[k], W1[k * DIM + tid], acc);
    __nv_bfloat16 h, l;
    split_bf16(acc, h, l);
    g_Bh[bid * DIM + tid] = h;
    g_Bl[bid * DIM + tid] = l;
    red[tid] = wih[tid] * b1[tid];
    __syncthreads();
    if (tid == 0) {
        float s = 0.f;
        for (int k = 0; k < DIM; k++) s += red[k];
        g_bc[bid] = s + b_ih[bid];
    }
}

// ---------------- HMMA GI GEMM (unchanged, occ 2) ----------------
#define GSM_BC  0
#define GSM_AH  1024
#define GSM_AL  (GSM_AH + 64 * 272)
#define GSM_BH  (GSM_AL + 64 * 272)
#define GSM_BL  (GSM_BH + 128 * 272)
#define GSMEM   (GSM_BL + 128 * 272)

__global__ __launch_bounds__(256, 2)
void gi_gemm_hmma(const float* __restrict__ X) {
    extern __shared__ char smem[];
    const uint32_t sbase = smem_u32(smem);
    const int tid = threadIdx.x;
    const int wid = tid >> 5, lane = tid & 31;
    const int nt = blockIdx.x;
    const int n0 = nt * 128;
    const int m0 = blockIdx.y * 64;

    const float4* Xf4 = (const float4*)X;
    #pragma unroll 4
    for (int s = tid; s < 2048; s += 256) {
        int row = s >> 5, q = s & 31;
        float4 v = Xf4[(size_t)(m0 + row) * 32 + q];
        __nv_bfloat16 h0, h1, h2, h3, l0, l1, l2, l3;
        split_bf16(v.x, h0, l0); split_bf16(v.y, h1, l1);
        split_bf16(v.z, h2, l2); split_bf16(v.w, h3, l3);
        __nv_bfloat162 hA(h0, h1), hB(h2, h3), lA(l0, l1), lB(l2, l3);
        int off = row * 272 + q * 8;
        *(uint2*)(smem + GSM_AH + off) = make_uint2(*(uint32_t*)&hA, *(uint32_t*)&hB);
        *(uint2*)(smem + GSM_AL + off) = make_uint2(*(uint32_t*)&lA, *(uint32_t*)&lB);
    }
    const uint4* Bh4 = (const uint4*)(g_Bh + nt * 16384);
    const uint4* Bl4 = (const uint4*)(g_Bl + nt * 16384);
    #pragma unroll 4
    for (int s = tid; s < 2048; s += 256) {
        int row = s >> 4, u = s & 15;
        int off = row * 272 + u * 16;
        *(uint4*)(smem + GSM_BH + off) = Bh4[s];
        *(uint4*)(smem + GSM_BL + off) = Bl4[s];
    }
    if (tid < 128) *(float*)(smem + GSM_BC + tid * 4) = g_bc[n0 + tid];
    __syncthreads();

    const int wm = wid & 1;
    const int wn = wid >> 1;
    const uint32_t aoff = (uint32_t)(wm * 32 + (lane & 15)) * 272 + ((lane >> 4) << 4);
    const uint32_t boff = (uint32_t)(wn * 32 + (lane & 7) + ((lane >> 4) << 3)) * 272
                        + (((lane >> 3) & 1) << 4);

    float C[2][4][4];
    #pragma unroll
    for (int mf = 0; mf < 2; mf++)
        #pragma unroll
        for (int nf = 0; nf < 4; nf++)
            #pragma unroll
            for (int q = 0; q < 4; q++) C[mf][nf][q] = 0.f;

    const uint32_t abase[3] = { sbase + GSM_AH, sbase + GSM_AH, sbase + GSM_AL };
    const uint32_t bbase[3] = { sbase + GSM_BH, sbase + GSM_BL, sbase + GSM_BH };

    #pragma unroll
    for (int p = 0; p < 3; p++) {
        const uint32_t ab = abase[p] + aoff;
        const uint32_t bb = bbase[p] + boff;
        #pragma unroll
        for (int ks = 0; ks < 8; ks++) {
            uint32_t a[2][4], b[2][4];
            ldsm4(a[0][0], a[0][1], a[0][2], a[0][3], ab + ks * 32);
            ldsm4(a[1][0], a[1][1], a[1][2], a[1][3], ab + 16 * 272 + ks * 32);
            ldsm4(b[0][0], b[0][1], b[0][2], b[0][3], bb + ks * 32);
            ldsm4(b[1][0], b[1][1], b[1][2], b[1][3], bb + 16 * 272 + ks * 32);
            #pragma unroll
            for (int mf = 0; mf < 2; mf++) {
                mma16816(C[mf][0], a[mf], b[0][0], b[0][1]);
                mma16816(C[mf][1], a[mf], b[0][2], b[0][3]);
                mma16816(C[mf][2], a[mf], b[1][0], b[1][1]);
                mma16816(C[mf][3], a[mf], b[1][2], b[1][3]);
            }
        }
    }

    const float* bcs = (const float*)(smem + GSM_BC);
    const int qrow = lane >> 2, qcol = (lane & 3) * 2;
    #pragma unroll
    for (int mf = 0; mf < 2; mf++) {
        int row = m0 + wm * 32 + mf * 16 + qrow;
        #pragma unroll
        for (int nf = 0; nf < 4; nf++) {
            int colL = wn * 32 + nf * 8 + qcol;
            float b0 = bcs[colL], b1 = bcs[colL + 1];
            float* d0 = g_GI + (size_t)row * GATES + n0 + colL;
            *(float2*)d0 = make_float2(C[mf][nf][0] + b0, C[mf][nf][1] + b1);
            float* d1 = g_GI + (size_t)(row + 8) * GATES + n0 + colL;
            *(float2*)d1 = make_float2(C[mf][nf][2] + b0, C[mf][nf][3] + b1);
        }
    }
}

// ---------------- HMMA GRU scan v7: split accumulator chains (6 x depth-8) ------
// 256 threads, 8 warps; warp w owns j in [16w,16w+16) for all 3 gates, full k.
// W_hi + W_lo fragments in registers (192 regs). Separate accumulators for the
// hi and lo passes -> 6 independent mma dep chains of depth 8 (was 3 x 16).
#define VW_LO   0                        // staging 384*272 = 104448
#define VW_HI   104448                   // staging 104448
#define VH      0                        // h ping-pong (reuses staging): 2 x 2048
#define VBH     4096                     // b_hh copy: 384 floats
#define VSMEM   (104448 * 2)

__global__ __launch_bounds__(256, 1)
void gru_scan_hmma(const float* __restrict__ W_hh, const float* __restrict__ b_hh,
                   float* __restrict__ out) {
    extern __shared__ char smem[];
    const uint32_t sbase = smem_u32(smem);
    const int tid = threadIdx.x, w = tid >> 5, lane = tid & 31;
    const int r0 = blockIdx.x * 4;

    // stage W_hh -> bf16 hi/lo, 272B-padded rows
    #pragma unroll 4
    for (int s = tid; s < 12288; s += 256) {
        int row = s >> 5, q = s & 31;
        float4 v = ((const float4*)W_hh)[s];
        __nv_bfloat16 h0, h1, h2, h3, l0, l1, l2, l3;
        split_bf16(v.x, h0, l0); split_bf16(v.y, h1, l1);
        split_bf16(v.z, h2, l2); split_bf16(v.w, h3, l3);
        __nv_bfloat162 hA(h0, h1), hB(h2, h3), lA(l0, l1), lB(l2, l3);
        int off = row * 272 + q * 8;
        *(uint2*)(smem + VW_HI + off) = make_uint2(*(uint32_t*)&hA, *(uint32_t*)&hB);
        *(uint2*)(smem + VW_LO + off) = make_uint2(*(uint32_t*)&lA, *(uint32_t*)&lB);
    }
    __syncthreads();

    // preload ALL W fragments: (hi + lo) x 3 gates x 8 ks = 192 regs
    uint32_t wh[3][8][4], wl[3][8][4];
    {
        const uint32_t lo_off = (uint32_t)(16 * w + (lane & 15)) * 272 + ((lane >> 4) << 4);
        #pragma unroll
        for (int g = 0; g < 3; g++)
            #pragma unroll
            for (int ks = 0; ks < 8; ks++) {
                ldsm4(wh[g][ks][0], wh[g][ks][1], wh[g][ks][2], wh[g][ks][3],
                      sbase + VW_HI + lo_off + (uint32_t)g * (128 * 272) + ks * 32);
                ldsm4(wl[g][ks][0], wl[g][ks][1], wl[g][ks][2], wl[g][ks][3],
                      sbase + VW_LO + lo_off + (uint32_t)g * (128 * 272) + ks * 32);
            }
    }
    __syncthreads();   // staging reads done -> reuse region for h ping-pong + b_hh

    // zero h phase 0; copy b_hh to smem
    for (int s = tid; s < 512; s += 256)
        ((uint32_t*)(smem + VH))[s] = 0;
    for (int s = tid; s < GATES; s += 256)
        *(float*)(smem + VBH + s * 4) = b_hh[s];
    __syncthreads();

    // lane -> (j, b) mapping
    const int jq = lane >> 2;
    const int j0 = 16 * w + jq, j1 = j0 + 8;
    const int bsel = lane & 3;
    const bool valid = (bsel < 2);
    const int b0 = 2 * bsel;

    const uint32_t bfb = sbase + VH + (uint32_t)(lane & 15) * 16;
    const float* bhs = (const float*)(smem + VBH);

    float hprev[4] = {0.f, 0.f, 0.f, 0.f};

    for (int t = 0; t < T_STEPS; t++) {
        const int cur = t & 1;

        // prefetch input gates (valid lanes; consumed post-mma -> latency hidden)
        float giv[3][4];
        #pragma unroll
        for (int q = 0; q < 4; q++) {
            if (valid) {
                int j = (q & 2) ? j1 : j0;
                int b = b0 + (q & 1);
                size_t base = ((size_t)t * BATCH + r0 + b) * GATES + j;
                giv[0][q] = g_GI[base];
                giv[1][q] = g_GI[base + DIM];
                giv[2][q] = g_GI[base + 2 * DIM];
            } else {
                giv[0][q] = giv[1][q] = giv[2][q] = 0.f;
            }
        }

        float Ch[3][4], Cl[3][4];
        #pragma unroll
        for (int g = 0; g < 3; g++)
            #pragma unroll
            for (int q = 0; q < 4; q++) { Ch[g][q] = 0.f; Cl[g][q] = 0.f; }

        // ks-outer; 6 independent accumulator chains (depth 8 each)
        const uint32_t hb = bfb + (uint32_t)cur * 2048;
        uint32_t bf0, bf1;
        ldsm2t(bf0, bf1, hb);
        #pragma unroll
        for (int ks = 0; ks < 8; ks++) {
            uint32_t nf0 = 0, nf1 = 0;
            if (ks < 7) ldsm2t(nf0, nf1, hb + (ks + 1) * 256);
            mma16816(Ch[0], wh[0][ks], bf0, bf1);
            mma16816(Ch[1], wh[1][ks], bf0, bf1);
            mma16816(Ch[2], wh[2][ks], bf0, bf1);
            mma16816(Cl[0], wl[0][ks], bf0, bf1);
            mma16816(Cl[1], wl[1][ks], bf0, bf1);
            mma16816(Cl[2], wl[2][ks], bf0, bf1);
            bf0 = nf0; bf1 = nf1;
        }

        // merge chains, fold h_lo columns, gates, publish h
        float hnew[4];
        #pragma unroll
        for (int q = 0; q < 4; q++) {
            float gr = Ch[0][q] + Cl[0][q]; gr += __shfl_xor_sync(0xffffffffu, gr, 2);
            float gz = Ch[1][q] + Cl[1][q]; gz += __shfl_xor_sync(0xffffffffu, gz, 2);
            float gn = Ch[2][q] + Cl[2][q]; gn += __shfl_xor_sync(0xffffffffu, gn, 2);
            int j = (q & 2) ? j1 : j0;
            float r = sigm_fast(gr + bhs[j] + giv[0][q]);
            float z = sigm_fast(gz + bhs[DIM + j] + giv[1][q]);
            float n = tanhf_fast(giv[2][q] + r * (gn + bhs[2 * DIM + j]));
            hnew[q] = n + z * (hprev[q] - n);
            hprev[q] = hnew[q];
        }
        if (valid) {
            const uint32_t nb = VH + (uint32_t)(cur ^ 1) * 2048;
            #pragma unroll
            for (int q = 0; q < 4; q++) {
                int j = (q & 2) ? j1 : j0;
                int b = b0 + (q & 1);
                __nv_bfloat16 hh, hl;
                split_bf16(hnew[q], hh, hl);
                *(__nv_bfloat16*)(smem + nb + j * 16 + b * 2) = hh;
                *(__nv_bfloat16*)(smem + nb + j * 16 + 8 + b * 2) = hl;
            }
        }
        __syncthreads();
    }

    if (valid) {
        #pragma unroll
        for (int q = 0; q < 4; q++) {
            int j = (q & 2) ? j1 : j0;
            int b = b0 + (q & 1);
            out[(r0 + b) * DIM + j] = hprev[q];
        }
    }
}

// ---------------- launch ----------------
extern "C" void kernel_launch(void* const* d_in, const int* in_sizes, int n_in,
                              void* d_out, int out_size) {
    const float* x    = (const float*)d_in[0];
    const float* W1   = (const float*)d_in[1];
    const float* b1   = (const float*)d_in[2];
    const float* W_ih = (const float*)d_in[3];
    const float* W_hh = (const float*)d_in[4];
    const float* b_ih = (const float*)d_in[5];
    const float* b_hh = (const float*)d_in[6];
    float* out = (float*)d_out;

    static bool attr_done = false;
    if (!attr_done) {
        cudaFuncSetAttribute(gi_gemm_hmma,
                             cudaFuncAttributeMaxDynamicSharedMemorySize, GSMEM);
        cudaFuncSetAttribute(gru_scan_hmma,
                             cudaFuncAttributeMaxDynamicSharedMemorySize, VSMEM);
        attr_done = true;
    }

    prep_kernel<<<GATES, DIM>>>(W1, b1, W_ih, b_ih);
    gi_gemm_hmma<<<dim3(3, 8192), 256, GSMEM>>>(x);
    gru_scan_hmma<<<128, 256, VSMEM>>>(W_hh, b_hh, out);
}